// round 1
// baseline (speedup 1.0000x reference)
#include <cuda_runtime.h>
#include <math.h>
#include <stdint.h>

// Problem constants
#define BDIM 2
#define SDIM 2048
#define DDIM 1024
#define HH   8
#define MROWS (BDIM*SDIM)          // 4096
static __device__ __constant__ float LAMBDA_INIT_F = 0.470713018343584f; // 0.8 - 0.6*exp(-0.6)

// ---------------- scratch (device globals: no runtime allocation allowed) ----------------
__device__ float g_lambda;
__device__ float g_qkv [MROWS * 3 * DDIM];           // 48 MB
__device__ float g_q1  [BDIM*HH*SDIM*64];
__device__ float g_k1  [BDIM*HH*SDIM*64];
__device__ float g_q2  [BDIM*HH*SDIM*64];
__device__ float g_k2  [BDIM*HH*SDIM*64];
__device__ float g_v   [BDIM*HH*SDIM*128];
__device__ float g_attn[MROWS * DDIM];
__device__ float g_tmp1[MROWS * DDIM];               // a + x (pre-LN1)
__device__ float g_h   [MROWS * DDIM];
__device__ float g_ff1 [MROWS * 4 * DDIM];           // 64 MB
__device__ float g_f2  [MROWS * DDIM];

// ---------------- lambda scalar ----------------
__global__ void lambda_kernel(const float* __restrict__ lq1, const float* __restrict__ lk1,
                              const float* __restrict__ lq2, const float* __restrict__ lk2)
{
    int lane = threadIdx.x;   // 32 threads
    float s1 = lq1[lane]*lk1[lane] + lq1[lane+32]*lk1[lane+32];
    float s2 = lq2[lane]*lk2[lane] + lq2[lane+32]*lk2[lane+32];
#pragma unroll
    for (int o = 16; o; o >>= 1) {
        s1 += __shfl_xor_sync(0xffffffffu, s1, o);
        s2 += __shfl_xor_sync(0xffffffffu, s2, o);
    }
    if (lane == 0) g_lambda = expf(s1) - expf(s2) + LAMBDA_INIT_F;
}

// ---------------- SGEMM: C[M,N] = A[M,K] @ B[K,N] (+bias[n]) (silu?) (+resid[m,n]) ----------
// BM=BN=128, BK=8, 256 threads, 8x8 microtile, global->reg prefetch.
// M,N multiples of 128; K multiple of 8.
__global__ __launch_bounds__(256) void sgemm_kernel(
    const float* __restrict__ A, const float* __restrict__ B, float* __restrict__ C,
    int M, int N, int K,
    const float* __restrict__ bias, const float* __restrict__ resid, int act)
{
    __shared__ float As[8][128];
    __shared__ float Bs[8][128];
    const int tid = threadIdx.x;
    const int tx = tid & 15;
    const int ty = tid >> 4;
    const int bm = blockIdx.y * 128;
    const int bn = blockIdx.x * 128;
    const int arow = tid >> 1;
    const int acol = (tid & 1) << 2;
    const int brow = tid >> 5;
    const int bcol = (tid & 31) << 2;

    const float* Ap = A + (size_t)(bm + arow) * K + acol;
    const float* Bp = B + (size_t)brow * N + bn + bcol;

    float4 aReg = *(const float4*)Ap;
    float4 bReg = *(const float4*)Bp;

    float acc[8][8];
#pragma unroll
    for (int i = 0; i < 8; i++)
#pragma unroll
        for (int j = 0; j < 8; j++) acc[i][j] = 0.f;

    const int nIter = K >> 3;
    for (int it = 0; it < nIter; it++) {
        As[acol+0][arow] = aReg.x; As[acol+1][arow] = aReg.y;
        As[acol+2][arow] = aReg.z; As[acol+3][arow] = aReg.w;
        *(float4*)&Bs[brow][bcol] = bReg;
        __syncthreads();
        if (it + 1 < nIter) {
            aReg = *(const float4*)(Ap + (it + 1) * 8);
            bReg = *(const float4*)(Bp + (size_t)(it + 1) * 8 * N);
        }
#pragma unroll
        for (int kk = 0; kk < 8; kk++) {
            float a[8], b[8];
#pragma unroll
            for (int i = 0; i < 8; i++) a[i] = As[kk][ty*8 + i];
#pragma unroll
            for (int j = 0; j < 8; j++) b[j] = Bs[kk][tx*8 + j];
#pragma unroll
            for (int i = 0; i < 8; i++)
#pragma unroll
                for (int j = 0; j < 8; j++) acc[i][j] = fmaf(a[i], b[j], acc[i][j]);
        }
        __syncthreads();
    }

    const int row0 = bm + ty*8;
    const int col0 = bn + tx*8;
#pragma unroll
    for (int i = 0; i < 8; i++) {
        size_t base = (size_t)(row0 + i) * N + col0;
#pragma unroll
        for (int jv = 0; jv < 2; jv++) {
            float4 o;
            o.x = acc[i][jv*4+0]; o.y = acc[i][jv*4+1];
            o.z = acc[i][jv*4+2]; o.w = acc[i][jv*4+3];
            if (bias) {
                float4 bv = *(const float4*)&bias[col0 + jv*4];
                o.x += bv.x; o.y += bv.y; o.z += bv.z; o.w += bv.w;
            }
            if (act == 1) {  // silu
                o.x = o.x / (1.f + __expf(-o.x));
                o.y = o.y / (1.f + __expf(-o.y));
                o.z = o.z / (1.f + __expf(-o.z));
                o.w = o.w / (1.f + __expf(-o.w));
            }
            if (resid) {
                float4 rv = *(const float4*)&resid[base + jv*4];
                o.x += rv.x; o.y += rv.y; o.z += rv.z; o.w += rv.w;
            }
            *(float4*)&C[base + jv*4] = o;
        }
    }
}

// ---------------- RoPE + head split + q2/k2 rmsnorm + V repack ----------------
// one block per (b,s) row; 8 warps; each warp handles one 64-dim head-component at a time.
__global__ __launch_bounds__(256) void rope_split_kernel(
    const float* __restrict__ sigmas, const float* __restrict__ lnq_w, const float* __restrict__ lnq_b)
{
    const int row = blockIdx.x;
    const int b = row / SDIM, s = row % SDIM;
    const float* base = g_qkv + (size_t)row * 3072;
    const int lane = threadIdx.x & 31;
    const int warp = threadIdx.x >> 5;

    // repack V: [b,s,1024] -> g_v[b,h,s,128]
    for (int idx = threadIdx.x; idx < 1024; idx += 256) {
        int h = idx >> 7, e = idx & 127;
        g_v[(((size_t)b*HH + h)*SDIM + s)*128 + e] = base[2048 + idx];
    }

    // rope factors for dim d=lane (<32 rotated, >=32 passthrough)
    int p = lane >> 1;
    float inv = (float)exp(-(double)p * 0.57564627324851148); // ln(10000)/16
    float fr = (float)s * inv;
    float c0 = cosf(fr), s0 = sinf(fr);

    for (int t = warp; t < 32; t += 8) {
        const int which = t >> 4;   // 0: q, 1: k
        const int h2 = t & 15;
        const float* src = base + which*1024 + h2*64;
        float x0 = src[lane];
        float x1 = src[lane + 32];
        float partner = src[lane ^ 1];
        float r0 = (lane & 1) ? fmaf(x0, c0,  partner * s0)
                              : fmaf(x0, c0, -partner * s0);
        const int h = h2 >> 1, comp = h2 & 1;
        size_t off = (((size_t)b*HH + h)*SDIM + s)*64;
        if (comp == 0) {
            float* dst = which ? g_k1 : g_q1;
            dst[off + lane]      = r0;
            dst[off + lane + 32] = x1;
        } else {
            float a0 = r0 + sigmas[b*64 + lane];
            float a1 = x1 + sigmas[b*64 + lane + 32];
            float ss = a0*a0 + a1*a1;
#pragma unroll
            for (int o = 16; o; o >>= 1) ss += __shfl_xor_sync(0xffffffffu, ss, o);
            float rms = rsqrtf(ss * (1.f/64.f) + 1e-8f);
            float* dst = which ? g_k2 : g_q2;
            dst[off + lane]      = fmaf(a0*rms, lnq_w[lane],      lnq_b[lane]);
            dst[off + lane + 32] = fmaf(a1*rms, lnq_w[lane+32],   lnq_b[lane+32]);
        }
    }
}

// ---------------- fused dual causal attention + diff + rmsnorm(128) ----------------
// grid (S/64, H, B), 256 threads (16x16). 64-row Q tile, 64-key tiles, online softmax x2.
#define TS 65   // padded stride for 64-wide smem tiles (bank-conflict avoidance)
__global__ __launch_bounds__(256) void attn_kernel(
    const float* __restrict__ ln_w, const float* __restrict__ ln_b)
{
    extern __shared__ float sm[];
    float* sQ1 = sm;
    float* sQ2 = sQ1 + 64*TS;
    float* sK1 = sQ2 + 64*TS;
    float* sK2 = sK1 + 64*TS;
    float* sS1 = sK2 + 64*TS;
    float* sS2 = sS1 + 64*TS;
    float* sV  = sS2 + 64*TS;     // 64 x 128, 16B-aligned (6*64*65*4 = 99840)
    float* m1  = sV + 64*128;
    float* l1  = m1 + 64;  float* al1 = l1 + 64;
    float* m2  = al1 + 64; float* l2  = m2 + 64; float* al2 = l2 + 64;

    const int qt = blockIdx.x, h = blockIdx.y, b = blockIdx.z;
    const int q0 = qt << 6;
    const int tid = threadIdx.x;
    const int tx = tid & 15, ty = tid >> 4;

    const size_t hoff = ((size_t)b*HH + h) * SDIM * 64;
    const float* Q1g = g_q1 + hoff + (size_t)q0 * 64;
    const float* Q2g = g_q2 + hoff + (size_t)q0 * 64;
    const float* K1g = g_k1 + hoff;
    const float* K2g = g_k2 + hoff;
    const float* Vg  = g_v + ((size_t)b*HH + h) * SDIM * 128;

    for (int i = tid; i < 4096; i += 256) {
        int r = i >> 6, c = i & 63;
        sQ1[r*TS + c] = Q1g[i];
        sQ2[r*TS + c] = Q2g[i];
    }
    if (tid < 64) { m1[tid] = -1e30f; l1[tid] = 0.f; m2[tid] = -1e30f; l2[tid] = 0.f; }

    float acc1[4][8], acc2[4][8];
#pragma unroll
    for (int i = 0; i < 4; i++)
#pragma unroll
        for (int j = 0; j < 8; j++) { acc1[i][j] = 0.f; acc2[i][j] = 0.f; }

    const float lam = g_lambda;

    for (int kt = 0; kt <= qt; kt++) {
        const int k0 = kt << 6;
        __syncthreads();
        for (int i = tid; i < 4096; i += 256) {
            int r = i >> 6, c = i & 63;
            sK1[r*TS + c] = K1g[(size_t)k0*64 + i];
            sK2[r*TS + c] = K2g[(size_t)k0*64 + i];
        }
        for (int i = tid; i < 2048; i += 256)
            ((float4*)sV)[i] = ((const float4*)(Vg + (size_t)k0*128))[i];
        __syncthreads();

        // ---- scores: S1 then S2 (sequential to limit live registers) ----
        {
            float sr[4][4];
#pragma unroll
            for (int i = 0; i < 4; i++)
#pragma unroll
                for (int j = 0; j < 4; j++) sr[i][j] = 0.f;
#pragma unroll 4
            for (int d = 0; d < 64; d++) {
                float q[4], k[4];
#pragma unroll
                for (int i = 0; i < 4; i++) q[i] = sQ1[(ty*4+i)*TS + d];
#pragma unroll
                for (int j = 0; j < 4; j++) k[j] = sK1[(tx*4+j)*TS + d];
#pragma unroll
                for (int i = 0; i < 4; i++)
#pragma unroll
                    for (int j = 0; j < 4; j++) sr[i][j] = fmaf(q[i], k[j], sr[i][j]);
            }
#pragma unroll
            for (int i = 0; i < 4; i++)
#pragma unroll
                for (int j = 0; j < 4; j++) {
                    int gr = q0 + ty*4 + i, gc = k0 + tx*4 + j;
                    float v = sr[i][j] * 0.125f;
                    if (gc > gr) v = -1e30f;
                    sS1[(ty*4+i)*TS + tx*4+j] = v;
                }
        }
        {
            float sr[4][4];
#pragma unroll
            for (int i = 0; i < 4; i++)
#pragma unroll
                for (int j = 0; j < 4; j++) sr[i][j] = 0.f;
#pragma unroll 4
            for (int d = 0; d < 64; d++) {
                float q[4], k[4];
#pragma unroll
                for (int i = 0; i < 4; i++) q[i] = sQ2[(ty*4+i)*TS + d];
#pragma unroll
                for (int j = 0; j < 4; j++) k[j] = sK2[(tx*4+j)*TS + d];
#pragma unroll
                for (int i = 0; i < 4; i++)
#pragma unroll
                    for (int j = 0; j < 4; j++) sr[i][j] = fmaf(q[i], k[j], sr[i][j]);
            }
#pragma unroll
            for (int i = 0; i < 4; i++)
#pragma unroll
                for (int j = 0; j < 4; j++) {
                    int gr = q0 + ty*4 + i, gc = k0 + tx*4 + j;
                    float v = sr[i][j] * 0.125f;
                    if (gc > gr) v = -1e30f;
                    sS2[(ty*4+i)*TS + tx*4+j] = v;
                }
        }
        __syncthreads();

        // ---- online softmax row update (128 threads: 64 rows x 2 branches) ----
        if (tid < 128) {
            const int r = tid & 63;
            float* Srow = (tid < 64 ? sS1 : sS2) + r*TS;
            float* mm = (tid < 64) ? m1 : m2;
            float* ll = (tid < 64) ? l1 : l2;
            float* aa = (tid < 64) ? al1 : al2;
            float tmax = -1e30f;
#pragma unroll 8
            for (int j = 0; j < 64; j++) tmax = fmaxf(tmax, Srow[j]);
            float mold = mm[r];
            float mnew = fmaxf(mold, tmax);
            float alpha = __expf(mold - mnew);
            float sum = 0.f;
#pragma unroll 8
            for (int j = 0; j < 64; j++) {
                float pv = __expf(Srow[j] - mnew);
                Srow[j] = pv;
                sum += pv;
            }
            ll[r] = ll[r]*alpha + sum;
            mm[r] = mnew;
            aa[r] = alpha;
        }
        __syncthreads();

        // ---- rescale + P@V for both branches ----
#pragma unroll
        for (int i = 0; i < 4; i++) {
            float a1v = al1[ty*4+i], a2v = al2[ty*4+i];
#pragma unroll
            for (int j = 0; j < 8; j++) { acc1[i][j] *= a1v; acc2[i][j] *= a2v; }
        }
#pragma unroll 4
        for (int k = 0; k < 64; k++) {
            float p1[4], p2[4];
#pragma unroll
            for (int i = 0; i < 4; i++) {
                p1[i] = sS1[(ty*4+i)*TS + k];
                p2[i] = sS2[(ty*4+i)*TS + k];
            }
            float4 va = *(const float4*)&sV[k*128 + tx*8];
            float4 vb = *(const float4*)&sV[k*128 + tx*8 + 4];
            float vv[8] = {va.x, va.y, va.z, va.w, vb.x, vb.y, vb.z, vb.w};
#pragma unroll
            for (int i = 0; i < 4; i++)
#pragma unroll
                for (int j = 0; j < 8; j++) {
                    acc1[i][j] = fmaf(p1[i], vv[j], acc1[i][j]);
                    acc2[i][j] = fmaf(p2[i], vv[j], acc2[i][j]);
                }
        }
    }

    // ---- epilogue: normalize, diff, rmsnorm over 128 cols, scale, store ----
    const float osc = 1.f - LAMBDA_INIT_F;
#pragma unroll
    for (int i = 0; i < 4; i++) {
        const int r = ty*4 + i;
        float inv1 = 1.f / l1[r];
        float inv2 = 1.f / l2[r];
        float dv[8];
        float ssq = 0.f;
#pragma unroll
        for (int j = 0; j < 8; j++) {
            float d = acc1[i][j]*inv1 - lam*(acc2[i][j]*inv2);
            dv[j] = d;
            ssq += d*d;
        }
#pragma unroll
        for (int o = 8; o; o >>= 1) ssq += __shfl_xor_sync(0xffffffffu, ssq, o);
        float rms = rsqrtf(ssq * (1.f/128.f) + 1e-8f);
        float* out = g_attn + ((size_t)(b*SDIM + q0 + r))*DDIM + h*128 + tx*8;
#pragma unroll
        for (int j = 0; j < 8; j++)
            out[j] = (dv[j]*rms*ln_w[tx*8+j] + ln_b[tx*8+j]) * osc;
    }
}

// ---------------- layernorm over 1024 ----------------
__global__ __launch_bounds__(256) void layernorm_kernel(
    const float* __restrict__ in, const float* __restrict__ w, const float* __restrict__ bb,
    float* __restrict__ out)
{
    __shared__ float red1[8], red2[8];
    const int row = blockIdx.x;
    const float* x = in + (size_t)row * DDIM;
    float v[4];
    float s = 0.f, s2 = 0.f;
#pragma unroll
    for (int it = 0; it < 4; it++) {
        float t = x[threadIdx.x + it*256];
        v[it] = t; s += t; s2 += t*t;
    }
#pragma unroll
    for (int o = 16; o; o >>= 1) {
        s  += __shfl_xor_sync(0xffffffffu, s,  o);
        s2 += __shfl_xor_sync(0xffffffffu, s2, o);
    }
    const int lane = threadIdx.x & 31, wp = threadIdx.x >> 5;
    if (lane == 0) { red1[wp] = s; red2[wp] = s2; }
    __syncthreads();
    if (wp == 0) {
        s  = (lane < 8) ? red1[lane] : 0.f;
        s2 = (lane < 8) ? red2[lane] : 0.f;
#pragma unroll
        for (int o = 4; o; o >>= 1) {
            s  += __shfl_xor_sync(0xffffffffu, s,  o);
            s2 += __shfl_xor_sync(0xffffffffu, s2, o);
        }
        if (lane == 0) { red1[0] = s * (1.f/1024.f); red2[0] = s2 * (1.f/1024.f); }
    }
    __syncthreads();
    const float mean = red1[0];
    const float var = red2[0] - mean*mean;
    const float rstd = rsqrtf(var + 1e-5f);
#pragma unroll
    for (int it = 0; it < 4; it++) {
        int c = threadIdx.x + it*256;
        out[(size_t)row*DDIM + c] = (v[it] - mean)*rstd*w[c] + bb[c];
    }
}

// ---------------- launch ----------------
extern "C" void kernel_launch(void* const* d_in, const int* in_sizes, int n_in,
                              void* d_out, int out_size)
{
    (void)in_sizes; (void)n_in; (void)out_size;
    const float* x      = (const float*)d_in[0];
    const float* sigmas = (const float*)d_in[1];
    const float* w_qkv  = (const float*)d_in[2];
    const float* w_out  = (const float*)d_in[3];
    const float* lq1    = (const float*)d_in[4];
    const float* lk1    = (const float*)d_in[5];
    const float* lq2    = (const float*)d_in[6];
    const float* lk2    = (const float*)d_in[7];
    const float* ln_w   = (const float*)d_in[8];
    const float* ln_b   = (const float*)d_in[9];
    const float* lnq_w  = (const float*)d_in[10];
    const float* lnq_b  = (const float*)d_in[11];
    const float* ln1_w  = (const float*)d_in[12];
    const float* ln1_b  = (const float*)d_in[13];
    const float* ln2_w  = (const float*)d_in[14];
    const float* ln2_b  = (const float*)d_in[15];
    const float* w1     = (const float*)d_in[16];
    const float* b1     = (const float*)d_in[17];
    const float* w2     = (const float*)d_in[18];
    const float* b2     = (const float*)d_in[19];
    float* out = (float*)d_out;

    void *p_qkv, *p_attn, *p_tmp1, *p_h, *p_ff1, *p_f2;
    cudaGetSymbolAddress(&p_qkv,  g_qkv);
    cudaGetSymbolAddress(&p_attn, g_attn);
    cudaGetSymbolAddress(&p_tmp1, g_tmp1);
    cudaGetSymbolAddress(&p_h,    g_h);
    cudaGetSymbolAddress(&p_ff1,  g_ff1);
    cudaGetSymbolAddress(&p_f2,   g_f2);

    lambda_kernel<<<1, 32>>>(lq1, lk1, lq2, lk2);

    // qkv = x @ w_qkv   [4096,1024]x[1024,3072]
    sgemm_kernel<<<dim3(3072/128, 4096/128), 256>>>(
        x, w_qkv, (float*)p_qkv, MROWS, 3072, 1024, nullptr, nullptr, 0);

    rope_split_kernel<<<MROWS, 256>>>(sigmas, lnq_w, lnq_b);

    const size_t attn_smem = (size_t)(6*64*TS + 64*128 + 6*64) * sizeof(float); // ~131 KB
    cudaFuncSetAttribute(attn_kernel, cudaFuncAttributeMaxDynamicSharedMemorySize, (int)attn_smem);
    attn_kernel<<<dim3(SDIM/64, HH, BDIM), 256, attn_smem>>>(ln_w, ln_b);

    // a = attn @ w_out + x
    sgemm_kernel<<<dim3(1024/128, 4096/128), 256>>>(
        (const float*)p_attn, w_out, (float*)p_tmp1, MROWS, 1024, 1024, nullptr, x, 0);

    layernorm_kernel<<<MROWS, 256>>>((const float*)p_tmp1, ln1_w, ln1_b, (float*)p_h);

    // ff1 = silu(h @ w1 + b1)
    sgemm_kernel<<<dim3(4096/128, 4096/128), 256>>>(
        (const float*)p_h, w1, (float*)p_ff1, MROWS, 4096, 1024, b1, nullptr, 1);

    // f2 = ff1 @ w2 + b2 + h
    sgemm_kernel<<<dim3(1024/128, 4096/128), 256>>>(
        (const float*)p_ff1, w2, (float*)p_f2, MROWS, 1024, 4096, b2, (const float*)p_h, 0);

    layernorm_kernel<<<MROWS, 256>>>((const float*)p_f2, ln2_w, ln2_b, out);
}

// round 3
// speedup vs baseline: 1.6304x; 1.6304x over previous
#include <cuda_runtime.h>
#include <cuda_bf16.h>
#include <math.h>
#include <stdint.h>

// Problem constants
#define BDIM 2
#define SDIM 2048
#define DDIM 1024
#define HH   8
#define MROWS (BDIM*SDIM)          // 4096
static __device__ __constant__ float LAMBDA_INIT_F = 0.470713018343584f; // 0.8 - 0.6*exp(-0.6)

// ================= scratch (device globals) =================
__device__ float g_lambda;
__device__ float g_qkv [MROWS * 3 * DDIM];
__device__ float g_q1  [BDIM*HH*SDIM*64];
__device__ float g_k1  [BDIM*HH*SDIM*64];
__device__ float g_q2  [BDIM*HH*SDIM*64];
__device__ float g_k2  [BDIM*HH*SDIM*64];
__device__ float g_v   [BDIM*HH*SDIM*128];
__device__ float g_tmp1[MROWS * DDIM];
__device__ float g_h   [MROWS * DDIM];
__device__ float g_f2  [MROWS * DDIM];

// bf16 hi/lo staging
__device__ __nv_bfloat16 g_xh[MROWS*DDIM],    g_xl[MROWS*DDIM];
__device__ __nv_bfloat16 g_wqkvTh[3*DDIM*DDIM], g_wqkvTl[3*DDIM*DDIM];   // [3072,1024]
__device__ __nv_bfloat16 g_woutTh[DDIM*DDIM],   g_woutTl[DDIM*DDIM];     // [1024,1024]
__device__ __nv_bfloat16 g_w1Th[4*DDIM*DDIM],   g_w1Tl[4*DDIM*DDIM];     // [4096,1024]
__device__ __nv_bfloat16 g_w2Th[DDIM*4*DDIM],   g_w2Tl[DDIM*4*DDIM];     // [1024,4096]
__device__ __nv_bfloat16 g_attnh[MROWS*DDIM],   g_attnl[MROWS*DDIM];
__device__ __nv_bfloat16 g_hh[MROWS*DDIM],      g_hl[MROWS*DDIM];
__device__ __nv_bfloat16 g_ff1h[MROWS*4*DDIM],  g_ff1l[MROWS*4*DDIM];

// ================= helpers =================
__device__ __forceinline__ uint32_t smem_u32(const void* p) {
    uint32_t a;
    asm("{ .reg .u64 t; cvta.to.shared.u64 t, %1; cvt.u32.u64 %0, t; }" : "=r"(a) : "l"(p));
    return a;
}
__device__ __forceinline__ void cpasync16(uint32_t dst, const void* src) {
    asm volatile("cp.async.cg.shared.global [%0], [%1], 16;" :: "r"(dst), "l"(src));
}
__device__ __forceinline__ void cp_commit() { asm volatile("cp.async.commit_group;" ::: "memory"); }
__device__ __forceinline__ void ldm4(uint32_t* r, uint32_t addr) {
    asm volatile("ldmatrix.sync.aligned.m8n8.x4.shared.b16 {%0,%1,%2,%3}, [%4];"
        : "=r"(r[0]), "=r"(r[1]), "=r"(r[2]), "=r"(r[3]) : "r"(addr));
}
__device__ __forceinline__ void mma16816(float* c, const uint32_t* a, uint32_t b0, uint32_t b1) {
    asm volatile("mma.sync.aligned.m16n8k16.row.col.f32.bf16.bf16.f32 "
        "{%0,%1,%2,%3}, {%4,%5,%6,%7}, {%8,%9}, {%0,%1,%2,%3};"
        : "+f"(c[0]), "+f"(c[1]), "+f"(c[2]), "+f"(c[3])
        : "r"(a[0]), "r"(a[1]), "r"(a[2]), "r"(a[3]), "r"(b0), "r"(b1));
}

// ================= lambda =================
__global__ void lambda_kernel(const float* __restrict__ lq1, const float* __restrict__ lk1,
                              const float* __restrict__ lq2, const float* __restrict__ lk2)
{
    int lane = threadIdx.x;
    float s1 = lq1[lane]*lk1[lane] + lq1[lane+32]*lk1[lane+32];
    float s2 = lq2[lane]*lk2[lane] + lq2[lane+32]*lk2[lane+32];
#pragma unroll
    for (int o = 16; o; o >>= 1) {
        s1 += __shfl_xor_sync(0xffffffffu, s1, o);
        s2 += __shfl_xor_sync(0xffffffffu, s2, o);
    }
    if (lane == 0) g_lambda = expf(s1) - expf(s2) + LAMBDA_INIT_F;
}

// ================= bf16 hi/lo split =================
__global__ __launch_bounds__(256) void split_kernel(const float* __restrict__ in,
    __nv_bfloat16* __restrict__ oh, __nv_bfloat16* __restrict__ ol, int n4)
{
    int i = blockIdx.x * 256 + threadIdx.x;
    if (i >= n4) return;
    float4 v = ((const float4*)in)[i];
    __nv_bfloat16 h0 = __float2bfloat16(v.x), h1 = __float2bfloat16(v.y);
    __nv_bfloat16 h2 = __float2bfloat16(v.z), h3 = __float2bfloat16(v.w);
    ((__nv_bfloat162*)oh)[2*i]   = __halves2bfloat162(h0, h1);
    ((__nv_bfloat162*)oh)[2*i+1] = __halves2bfloat162(h2, h3);
    ((__nv_bfloat162*)ol)[2*i]   = __floats2bfloat162_rn(v.x - __bfloat162float(h0), v.y - __bfloat162float(h1));
    ((__nv_bfloat162*)ol)[2*i+1] = __floats2bfloat162_rn(v.z - __bfloat162float(h2), v.w - __bfloat162float(h3));
}

// ================= transpose + split: in[K,N] fp32 -> out[N,K] bf16 hi/lo =================
__global__ __launch_bounds__(256) void transpose_split_kernel(const float* __restrict__ in,
    __nv_bfloat16* __restrict__ oh, __nv_bfloat16* __restrict__ ol, int K, int N)
{
    __shared__ float t[32][33];
    const int k0 = blockIdx.y*32, n0 = blockIdx.x*32;
    const int tx = threadIdx.x, ty = threadIdx.y;
#pragma unroll
    for (int i = 0; i < 4; i++)
        t[ty + i*8][tx] = in[(size_t)(k0 + ty + i*8)*N + n0 + tx];
    __syncthreads();
#pragma unroll
    for (int i = 0; i < 4; i++) {
        int n = n0 + ty + i*8, k = k0 + tx;
        float v = t[tx][ty + i*8];
        __nv_bfloat16 hv = __float2bfloat16(v);
        oh[(size_t)n*K + k] = hv;
        ol[(size_t)n*K + k] = __float2bfloat16(v - __bfloat162float(hv));
    }
}

// ================= mma.sync bf16x3 GEMM =================
// C[M,N] = (Ah+Al)[M,K] @ (Bh+Bl)[N,K]^T, fp32 accum, 3-term split product.
// 128x128 CTA tile, K-chunk 32, 2-stage cp.async pipeline, 8 warps (4m x 2n).
// smem per tile: 128 rows x 80 bytes (64B data + 16B pad) = 10240 B; 4 tiles/stage.
#define TILE_B   10240
#define STAGE_B  40960
#define GEMM_SMEM (2*STAGE_B)

__global__ __launch_bounds__(256) void gemm_mma_kernel(
    const __nv_bfloat16* __restrict__ Ah, const __nv_bfloat16* __restrict__ Al,
    const __nv_bfloat16* __restrict__ Bh, const __nv_bfloat16* __restrict__ Bl,
    float* __restrict__ Cf, __nv_bfloat16* __restrict__ Ch, __nv_bfloat16* __restrict__ Cl,
    int M, int N, int K,
    const float* __restrict__ bias, const float* __restrict__ resid, int act)
{
    extern __shared__ char smem[];
    const uint32_t sb = smem_u32(smem);
    const int tid = threadIdx.x;
    const int lane = tid & 31;
    const int wid = tid >> 5;
    const int bm = blockIdx.y * 128;
    const int bn = blockIdx.x * 128;
    const int wm = wid >> 1;     // 0..3
    const int wn = wid & 1;      // 0..1

    // ---- loader indexing: thread t loads 32B of row (t>>1), half (t&1) for each tile
    const int lrow  = tid >> 1;
    const int lhalf = (tid & 1) * 32;  // byte offset within 64B row
    const size_t rowB = (size_t)K * 2;
    const char* gAh = (const char*)Ah + (size_t)(bm + lrow) * rowB + lhalf;
    const char* gAl = (const char*)Al + (size_t)(bm + lrow) * rowB + lhalf;
    const char* gBh = (const char*)Bh + (size_t)(bn + lrow) * rowB + lhalf;
    const char* gBl = (const char*)Bl + (size_t)(bn + lrow) * rowB + lhalf;
    const uint32_t sdst = sb + (uint32_t)lrow * 80u + (uint32_t)lhalf;

    const int nChunks = K >> 5;

    // ---- prologue: chunk 0 -> stage 0
    {
        uint32_t d = sdst;
        cpasync16(d,            gAh);      cpasync16(d + 16,            gAh + 16);
        cpasync16(d + TILE_B,   gAl);      cpasync16(d + TILE_B + 16,   gAl + 16);
        cpasync16(d + 2*TILE_B, gBh);      cpasync16(d + 2*TILE_B + 16, gBh + 16);
        cpasync16(d + 3*TILE_B, gBl);      cpasync16(d + 3*TILE_B + 16, gBl + 16);
        cp_commit();
    }

    float acc[2][8][4];
#pragma unroll
    for (int i = 0; i < 2; i++)
#pragma unroll
        for (int j = 0; j < 8; j++)
#pragma unroll
            for (int k = 0; k < 4; k++) acc[i][j][k] = 0.f;

    // fragment address components (per lane)
    const int lt = lane >> 3, lj = lane & 7;
    const uint32_t a_row = (uint32_t)(wm*32 + (lt & 1)*8 + lj) * 80u;
    const uint32_t a_col = (uint32_t)((lt >> 1) * 8) * 2u;
    const uint32_t b_row = (uint32_t)(wn*64 + (lt >> 1)*8 + lj) * 80u;
    const uint32_t b_col = (uint32_t)((lt & 1) * 8) * 2u;

    for (int c = 0; c < nChunks; c++) {
        if (c + 1 < nChunks) {
            const uint32_t d = sdst + (uint32_t)((c + 1) & 1) * STAGE_B;
            const size_t go = (size_t)(c + 1) * 64;
            cpasync16(d,            gAh + go);      cpasync16(d + 16,            gAh + go + 16);
            cpasync16(d + TILE_B,   gAl + go);      cpasync16(d + TILE_B + 16,   gAl + go + 16);
            cpasync16(d + 2*TILE_B, gBh + go);      cpasync16(d + 2*TILE_B + 16, gBh + go + 16);
            cpasync16(d + 3*TILE_B, gBl + go);      cpasync16(d + 3*TILE_B + 16, gBl + go + 16);
            cp_commit();
            asm volatile("cp.async.wait_group 1;" ::: "memory");
        } else {
            asm volatile("cp.async.wait_group 0;" ::: "memory");
        }
        __syncthreads();

        const uint32_t base = sb + (uint32_t)(c & 1) * STAGE_B;
#pragma unroll
        for (int ks = 0; ks < 2; ks++) {
            const uint32_t kofs = (uint32_t)ks * 32u;   // 16 bf16 = 32 bytes
            uint32_t afh[2][4], afl[2][4];
#pragma unroll
            for (int ma = 0; ma < 2; ma++) {
                ldm4(afh[ma], base +            a_row + (uint32_t)ma*16u*80u + a_col + kofs);
                ldm4(afl[ma], base + TILE_B   + a_row + (uint32_t)ma*16u*80u + a_col + kofs);
            }
            uint32_t bfh[4][4], bfl[4][4];
#pragma unroll
            for (int g = 0; g < 4; g++) {
                ldm4(bfh[g], base + 2*TILE_B + b_row + (uint32_t)g*16u*80u + b_col + kofs);
                ldm4(bfl[g], base + 3*TILE_B + b_row + (uint32_t)g*16u*80u + b_col + kofs);
            }
#pragma unroll
            for (int ma = 0; ma < 2; ma++)
#pragma unroll
                for (int g = 0; g < 4; g++)
#pragma unroll
                    for (int hf = 0; hf < 2; hf++) {
                        float* C = acc[ma][g*2 + hf];
                        mma16816(C, afh[ma], bfh[g][hf*2], bfh[g][hf*2+1]);
                        mma16816(C, afh[ma], bfl[g][hf*2], bfl[g][hf*2+1]);
                        mma16816(C, afl[ma], bfh[g][hf*2], bfh[g][hf*2+1]);
                    }
        }
        __syncthreads();
    }

    // ---- epilogue
#pragma unroll
    for (int ma = 0; ma < 2; ma++)
#pragma unroll
        for (int na = 0; na < 8; na++) {
            const int r0 = bm + wm*32 + ma*16 + (lane >> 2);
            const int c0 = bn + wn*64 + na*8 + 2*(lane & 3);
#pragma unroll
            for (int half = 0; half < 2; half++) {
                const int r = r0 + half*8;
                float v0 = acc[ma][na][half*2 + 0];
                float v1 = acc[ma][na][half*2 + 1];
                if (bias) { v0 += bias[c0]; v1 += bias[c0 + 1]; }
                if (act) {
                    v0 = v0 / (1.f + __expf(-v0));
                    v1 = v1 / (1.f + __expf(-v1));
                }
                const size_t o = (size_t)r * N + c0;
                if (resid) { v0 += resid[o]; v1 += resid[o + 1]; }
                if (Cf) { float2 f2o; f2o.x = v0; f2o.y = v1; *(float2*)&Cf[o] = f2o; }
                if (Ch) {
                    __nv_bfloat16 h0 = __float2bfloat16(v0);
                    __nv_bfloat16 h1 = __float2bfloat16(v1);
                    *(__nv_bfloat162*)&Ch[o] = __halves2bfloat162(h0, h1);
                    *(__nv_bfloat162*)&Cl[o] = __floats2bfloat162_rn(
                        v0 - __bfloat162float(h0), v1 - __bfloat162float(h1));
                }
            }
        }
}

// ================= RoPE + head split + q2/k2 rmsnorm + V repack =================
__global__ __launch_bounds__(256) void rope_split_kernel(
    const float* __restrict__ sigmas, const float* __restrict__ lnq_w, const float* __restrict__ lnq_b)
{
    const int row = blockIdx.x;
    const int b = row / SDIM, s = row % SDIM;
    const float* base = g_qkv + (size_t)row * 3072;
    const int lane = threadIdx.x & 31;
    const int warp = threadIdx.x >> 5;

    for (int idx = threadIdx.x; idx < 1024; idx += 256) {
        int h = idx >> 7, e = idx & 127;
        g_v[(((size_t)b*HH + h)*SDIM + s)*128 + e] = base[2048 + idx];
    }

    int p = lane >> 1;
    float inv = (float)exp(-(double)p * 0.57564627324851148);
    float fr = (float)s * inv;
    float c0 = cosf(fr), s0 = sinf(fr);

    for (int t = warp; t < 32; t += 8) {
        const int which = t >> 4;
        const int h2 = t & 15;
        const float* src = base + which*1024 + h2*64;
        float x0 = src[lane];
        float x1 = src[lane + 32];
        float partner = src[lane ^ 1];
        float r0 = (lane & 1) ? fmaf(x0, c0,  partner * s0)
                              : fmaf(x0, c0, -partner * s0);
        const int h = h2 >> 1, comp = h2 & 1;
        size_t off = (((size_t)b*HH + h)*SDIM + s)*64;
        if (comp == 0) {
            float* dst = which ? g_k1 : g_q1;
            dst[off + lane]      = r0;
            dst[off + lane + 32] = x1;
        } else {
            float a0 = r0 + sigmas[b*64 + lane];
            float a1 = x1 + sigmas[b*64 + lane + 32];
            float ss = a0*a0 + a1*a1;
#pragma unroll
            for (int o = 16; o; o >>= 1) ss += __shfl_xor_sync(0xffffffffu, ss, o);
            float rms = rsqrtf(ss * (1.f/64.f) + 1e-8f);
            float* dst = which ? g_k2 : g_q2;
            dst[off + lane]      = fmaf(a0*rms, lnq_w[lane],      lnq_b[lane]);
            dst[off + lane + 32] = fmaf(a1*rms, lnq_w[lane+32],   lnq_b[lane+32]);
        }
    }
}

// ================= fused dual causal attention + diff + rmsnorm(128) =================
#define TS 65
__global__ __launch_bounds__(256) void attn_kernel(
    const float* __restrict__ ln_w, const float* __restrict__ ln_b)
{
    extern __shared__ float sm[];
    float* sQ1 = sm;
    float* sQ2 = sQ1 + 64*TS;
    float* sK1 = sQ2 + 64*TS;
    float* sK2 = sK1 + 64*TS;
    float* sS1 = sK2 + 64*TS;
    float* sS2 = sS1 + 64*TS;
    float* sV  = sS2 + 64*TS;
    float* m1  = sV + 64*128;
    float* l1  = m1 + 64;  float* al1 = l1 + 64;
    float* m2  = al1 + 64; float* l2  = m2 + 64; float* al2 = l2 + 64;

    const int qt = blockIdx.x, h = blockIdx.y, b = blockIdx.z;
    const int q0 = qt << 6;
    const int tid = threadIdx.x;
    const int tx = tid & 15, ty = tid >> 4;

    const size_t hoff = ((size_t)b*HH + h) * SDIM * 64;
    const float* Q1g = g_q1 + hoff + (size_t)q0 * 64;
    const float* Q2g = g_q2 + hoff + (size_t)q0 * 64;
    const float* K1g = g_k1 + hoff;
    const float* K2g = g_k2 + hoff;
    const float* Vg  = g_v + ((size_t)b*HH + h) * SDIM * 128;

    for (int i = tid; i < 4096; i += 256) {
        int r = i >> 6, c = i & 63;
        sQ1[r*TS + c] = Q1g[i];
        sQ2[r*TS + c] = Q2g[i];
    }
    if (tid < 64) { m1[tid] = -1e30f; l1[tid] = 0.f; m2[tid] = -1e30f; l2[tid] = 0.f; }

    float acc1[4][8], acc2[4][8];
#pragma unroll
    for (int i = 0; i < 4; i++)
#pragma unroll
        for (int j = 0; j < 8; j++) { acc1[i][j] = 0.f; acc2[i][j] = 0.f; }

    const float lam = g_lambda;

    for (int kt = 0; kt <= qt; kt++) {
        const int k0 = kt << 6;
        __syncthreads();
        for (int i = tid; i < 4096; i += 256) {
            int r = i >> 6, c = i & 63;
            sK1[r*TS + c] = K1g[(size_t)k0*64 + i];
            sK2[r*TS + c] = K2g[(size_t)k0*64 + i];
        }
        for (int i = tid; i < 2048; i += 256)
            ((float4*)sV)[i] = ((const float4*)(Vg + (size_t)k0*128))[i];
        __syncthreads();

        {
            float sr[4][4];
#pragma unroll
            for (int i = 0; i < 4; i++)
#pragma unroll
                for (int j = 0; j < 4; j++) sr[i][j] = 0.f;
#pragma unroll 4
            for (int d = 0; d < 64; d++) {
                float q[4], k[4];
#pragma unroll
                for (int i = 0; i < 4; i++) q[i] = sQ1[(ty*4+i)*TS + d];
#pragma unroll
                for (int j = 0; j < 4; j++) k[j] = sK1[(tx*4+j)*TS + d];
#pragma unroll
                for (int i = 0; i < 4; i++)
#pragma unroll
                    for (int j = 0; j < 4; j++) sr[i][j] = fmaf(q[i], k[j], sr[i][j]);
            }
#pragma unroll
            for (int i = 0; i < 4; i++)
#pragma unroll
                for (int j = 0; j < 4; j++) {
                    int gr = q0 + ty*4 + i, gc = k0 + tx*4 + j;
                    float v = sr[i][j] * 0.125f;
                    if (gc > gr) v = -1e30f;
                    sS1[(ty*4+i)*TS + tx*4+j] = v;
                }
        }
        {
            float sr[4][4];
#pragma unroll
            for (int i = 0; i < 4; i++)
#pragma unroll
                for (int j = 0; j < 4; j++) sr[i][j] = 0.f;
#pragma unroll 4
            for (int d = 0; d < 64; d++) {
                float q[4], k[4];
#pragma unroll
                for (int i = 0; i < 4; i++) q[i] = sQ2[(ty*4+i)*TS + d];
#pragma unroll
                for (int j = 0; j < 4; j++) k[j] = sK2[(tx*4+j)*TS + d];
#pragma unroll
                for (int i = 0; i < 4; i++)
#pragma unroll
                    for (int j = 0; j < 4; j++) sr[i][j] = fmaf(q[i], k[j], sr[i][j]);
            }
#pragma unroll
            for (int i = 0; i < 4; i++)
#pragma unroll
                for (int j = 0; j < 4; j++) {
                    int gr = q0 + ty*4 + i, gc = k0 + tx*4 + j;
                    float v = sr[i][j] * 0.125f;
                    if (gc > gr) v = -1e30f;
                    sS2[(ty*4+i)*TS + tx*4+j] = v;
                }
        }
        __syncthreads();

        if (tid < 128) {
            const int r = tid & 63;
            float* Srow = (tid < 64 ? sS1 : sS2) + r*TS;
            float* mm = (tid < 64) ? m1 : m2;
            float* ll = (tid < 64) ? l1 : l2;
            float* aa = (tid < 64) ? al1 : al2;
            float tmax = -1e30f;
#pragma unroll 8
            for (int j = 0; j < 64; j++) tmax = fmaxf(tmax, Srow[j]);
            float mold = mm[r];
            float mnew = fmaxf(mold, tmax);
            float alpha = __expf(mold - mnew);
            float sum = 0.f;
#pragma unroll 8
            for (int j = 0; j < 64; j++) {
                float pv = __expf(Srow[j] - mnew);
                Srow[j] = pv;
                sum += pv;
            }
            ll[r] = ll[r]*alpha + sum;
            mm[r] = mnew;
            aa[r] = alpha;
        }
        __syncthreads();

#pragma unroll
        for (int i = 0; i < 4; i++) {
            float a1v = al1[ty*4+i], a2v = al2[ty*4+i];
#pragma unroll
            for (int j = 0; j < 8; j++) { acc1[i][j] *= a1v; acc2[i][j] *= a2v; }
        }
#pragma unroll 4
        for (int k = 0; k < 64; k++) {
            float p1[4], p2[4];
#pragma unroll
            for (int i = 0; i < 4; i++) {
                p1[i] = sS1[(ty*4+i)*TS + k];
                p2[i] = sS2[(ty*4+i)*TS + k];
            }
            float4 va = *(const float4*)&sV[k*128 + tx*8];
            float4 vb = *(const float4*)&sV[k*128 + tx*8 + 4];
            float vv[8] = {va.x, va.y, va.z, va.w, vb.x, vb.y, vb.z, vb.w};
#pragma unroll
            for (int i = 0; i < 4; i++)
#pragma unroll
                for (int j = 0; j < 8; j++) {
                    acc1[i][j] = fmaf(p1[i], vv[j], acc1[i][j]);
                    acc2[i][j] = fmaf(p2[i], vv[j], acc2[i][j]);
                }
        }
    }

    const float osc = 1.f - LAMBDA_INIT_F;
#pragma unroll
    for (int i = 0; i < 4; i++) {
        const int r = ty*4 + i;
        float inv1 = 1.f / l1[r];
        float inv2 = 1.f / l2[r];
        float dv[8];
        float ssq = 0.f;
#pragma unroll
        for (int j = 0; j < 8; j++) {
            float d = acc1[i][j]*inv1 - lam*(acc2[i][j]*inv2);
            dv[j] = d;
            ssq += d*d;
        }
#pragma unroll
        for (int o = 8; o; o >>= 1) ssq += __shfl_xor_sync(0xffffffffu, ssq, o);
        float rms = rsqrtf(ssq * (1.f/128.f) + 1e-8f);
        size_t obase = ((size_t)(b*SDIM + q0 + r))*DDIM + h*128 + tx*8;
#pragma unroll
        for (int j = 0; j < 8; j++) {
            float val = (dv[j]*rms*ln_w[tx*8+j] + ln_b[tx*8+j]) * osc;
            __nv_bfloat16 hv = __float2bfloat16(val);
            g_attnh[obase + j] = hv;
            g_attnl[obase + j] = __float2bfloat16(val - __bfloat162float(hv));
        }
    }
}

// ================= layernorm over 1024 (+ optional bf16 split out) =================
__global__ __launch_bounds__(256) void layernorm_kernel(
    const float* __restrict__ in, const float* __restrict__ w, const float* __restrict__ bb,
    float* __restrict__ out, __nv_bfloat16* __restrict__ oh, __nv_bfloat16* __restrict__ ol)
{
    __shared__ float red1[8], red2[8];
    const int row = blockIdx.x;
    const float* x = in + (size_t)row * DDIM;
    float v[4];
    float s = 0.f, s2 = 0.f;
#pragma unroll
    for (int it = 0; it < 4; it++) {
        float t = x[threadIdx.x + it*256];
        v[it] = t; s += t; s2 += t*t;
    }
#pragma unroll
    for (int o = 16; o; o >>= 1) {
        s  += __shfl_xor_sync(0xffffffffu, s,  o);
        s2 += __shfl_xor_sync(0xffffffffu, s2, o);
    }
    const int lane = threadIdx.x & 31, wp = threadIdx.x >> 5;
    if (lane == 0) { red1[wp] = s; red2[wp] = s2; }
    __syncthreads();
    if (wp == 0) {
        s  = (lane < 8) ? red1[lane] : 0.f;
        s2 = (lane < 8) ? red2[lane] : 0.f;
#pragma unroll
        for (int o = 4; o; o >>= 1) {
            s  += __shfl_xor_sync(0xffffffffu, s,  o);
            s2 += __shfl_xor_sync(0xffffffffu, s2, o);
        }
        if (lane == 0) { red1[0] = s * (1.f/1024.f); red2[0] = s2 * (1.f/1024.f); }
    }
    __syncthreads();
    const float mean = red1[0];
    const float var = red2[0] - mean*mean;
    const float rstd = rsqrtf(var + 1e-5f);
#pragma unroll
    for (int it = 0; it < 4; it++) {
        int c = threadIdx.x + it*256;
        size_t idx = (size_t)row*DDIM + c;
        float y = (v[it] - mean)*rstd*w[c] + bb[c];
        out[idx] = y;
        if (oh) {
            __nv_bfloat16 hv = __float2bfloat16(y);
            oh[idx] = hv;
            ol[idx] = __float2bfloat16(y - __bfloat162float(hv));
        }
    }
}

// ================= launch =================
extern "C" void kernel_launch(void* const* d_in, const int* in_sizes, int n_in,
                              void* d_out, int out_size)
{
    (void)in_sizes; (void)n_in; (void)out_size;
    const float* x      = (const float*)d_in[0];
    const float* sigmas = (const float*)d_in[1];
    const float* w_qkv  = (const float*)d_in[2];
    const float* w_out  = (const float*)d_in[3];
    const float* lq1    = (const float*)d_in[4];
    const float* lk1    = (const float*)d_in[5];
    const float* lq2    = (const float*)d_in[6];
    const float* lk2    = (const float*)d_in[7];
    const float* ln_w   = (const float*)d_in[8];
    const float* ln_b   = (const float*)d_in[9];
    const float* lnq_w  = (const float*)d_in[10];
    const float* lnq_b  = (const float*)d_in[11];
    const float* ln1_w  = (const float*)d_in[12];
    const float* ln1_b  = (const float*)d_in[13];
    const float* ln2_w  = (const float*)d_in[14];
    const float* ln2_b  = (const float*)d_in[15];
    const float* w1     = (const float*)d_in[16];
    const float* b1     = (const float*)d_in[17];
    const float* w2     = (const float*)d_in[18];
    const float* b2     = (const float*)d_in[19];
    float* out = (float*)d_out;

    void *p_qkv, *p_tmp1, *p_h, *p_f2;
    void *p_xh, *p_xl, *p_wqkvTh, *p_wqkvTl, *p_woutTh, *p_woutTl;
    void *p_w1Th, *p_w1Tl, *p_w2Th, *p_w2Tl;
    void *p_attnh, *p_attnl, *p_hh, *p_hl, *p_ff1h, *p_ff1l;
    cudaGetSymbolAddress(&p_qkv,  g_qkv);
    cudaGetSymbolAddress(&p_tmp1, g_tmp1);
    cudaGetSymbolAddress(&p_h,    g_h);
    cudaGetSymbolAddress(&p_f2,   g_f2);
    cudaGetSymbolAddress(&p_xh, g_xh);       cudaGetSymbolAddress(&p_xl, g_xl);
    cudaGetSymbolAddress(&p_wqkvTh, g_wqkvTh); cudaGetSymbolAddress(&p_wqkvTl, g_wqkvTl);
    cudaGetSymbolAddress(&p_woutTh, g_woutTh); cudaGetSymbolAddress(&p_woutTl, g_woutTl);
    cudaGetSymbolAddress(&p_w1Th, g_w1Th);   cudaGetSymbolAddress(&p_w1Tl, g_w1Tl);
    cudaGetSymbolAddress(&p_w2Th, g_w2Th);   cudaGetSymbolAddress(&p_w2Tl, g_w2Tl);
    cudaGetSymbolAddress(&p_attnh, g_attnh); cudaGetSymbolAddress(&p_attnl, g_attnl);
    cudaGetSymbolAddress(&p_hh, g_hh);       cudaGetSymbolAddress(&p_hl, g_hl);
    cudaGetSymbolAddress(&p_ff1h, g_ff1h);   cudaGetSymbolAddress(&p_ff1l, g_ff1l);

    cudaFuncSetAttribute(gemm_mma_kernel, cudaFuncAttributeMaxDynamicSharedMemorySize, GEMM_SMEM);

    lambda_kernel<<<1, 32>>>(lq1, lk1, lq2, lk2);

    // stage inputs/weights as bf16 hi/lo
    split_kernel<<<(MROWS*DDIM/4 + 255)/256, 256>>>(x, (__nv_bfloat16*)p_xh, (__nv_bfloat16*)p_xl, MROWS*DDIM/4);
    transpose_split_kernel<<<dim3(3072/32, 1024/32), dim3(32,8)>>>(w_qkv, (__nv_bfloat16*)p_wqkvTh, (__nv_bfloat16*)p_wqkvTl, 1024, 3072);
    transpose_split_kernel<<<dim3(1024/32, 1024/32), dim3(32,8)>>>(w_out, (__nv_bfloat16*)p_woutTh, (__nv_bfloat16*)p_woutTl, 1024, 1024);
    transpose_split_kernel<<<dim3(4096/32, 1024/32), dim3(32,8)>>>(w1, (__nv_bfloat16*)p_w1Th, (__nv_bfloat16*)p_w1Tl, 1024, 4096);
    transpose_split_kernel<<<dim3(1024/32, 4096/32), dim3(32,8)>>>(w2, (__nv_bfloat16*)p_w2Th, (__nv_bfloat16*)p_w2Tl, 4096, 1024);

    // qkv = x @ w_qkv
    gemm_mma_kernel<<<dim3(3072/128, 4096/128), 256, GEMM_SMEM>>>(
        (const __nv_bfloat16*)p_xh, (const __nv_bfloat16*)p_xl,
        (const __nv_bfloat16*)p_wqkvTh, (const __nv_bfloat16*)p_wqkvTl,
        (float*)p_qkv, nullptr, nullptr, MROWS, 3072, 1024, nullptr, nullptr, 0);

    rope_split_kernel<<<MROWS, 256>>>(sigmas, lnq_w, lnq_b);

    const size_t attn_smem = (size_t)(6*64*TS + 64*128 + 6*64) * sizeof(float);
    cudaFuncSetAttribute(attn_kernel, cudaFuncAttributeMaxDynamicSharedMemorySize, (int)attn_smem);
    attn_kernel<<<dim3(SDIM/64, HH, BDIM), 256, attn_smem>>>(ln_w, ln_b);

    // tmp1 = attn @ w_out + x
    gemm_mma_kernel<<<dim3(1024/128, 4096/128), 256, GEMM_SMEM>>>(
        (const __nv_bfloat16*)p_attnh, (const __nv_bfloat16*)p_attnl,
        (const __nv_bfloat16*)p_woutTh, (const __nv_bfloat16*)p_woutTl,
        (float*)p_tmp1, nullptr, nullptr, MROWS, 1024, 1024, nullptr, x, 0);

    layernorm_kernel<<<MROWS, 256>>>((const float*)p_tmp1, ln1_w, ln1_b,
        (float*)p_h, (__nv_bfloat16*)p_hh, (__nv_bfloat16*)p_hl);

    // ff1 = silu(h @ w1 + b1) -> bf16 split only
    gemm_mma_kernel<<<dim3(4096/128, 4096/128), 256, GEMM_SMEM>>>(
        (const __nv_bfloat16*)p_hh, (const __nv_bfloat16*)p_hl,
        (const __nv_bfloat16*)p_w1Th, (const __nv_bfloat16*)p_w1Tl,
        nullptr, (__nv_bfloat16*)p_ff1h, (__nv_bfloat16*)p_ff1l, MROWS, 4096, 1024, b1, nullptr, 1);

    // f2 = ff1 @ w2 + b2 + h
    gemm_mma_kernel<<<dim3(1024/128, 4096/128), 256, GEMM_SMEM>>>(
        (const __nv_bfloat16*)p_ff1h, (const __nv_bfloat16*)p_ff1l,
        (const __nv_bfloat16*)p_w2Th, (const __nv_bfloat16*)p_w2Tl,
        (float*)p_f2, nullptr, nullptr, MROWS, 1024, 4096, b2, (const float*)p_h, 0);

    layernorm_kernel<<<MROWS, 256>>>((const float*)p_f2, ln2_w, ln2_b, out, nullptr, nullptr);
}

// round 4
// speedup vs baseline: 2.5035x; 1.5355x over previous
#include <cuda_runtime.h>
#include <cuda_bf16.h>
#include <math.h>
#include <stdint.h>

// Problem constants
#define BDIM 2
#define SDIM 2048
#define DDIM 1024
#define HH   8
#define MROWS (BDIM*SDIM)          // 4096
static __device__ __constant__ float LAMBDA_INIT_F = 0.470713018343584f; // 0.8 - 0.6*exp(-0.6)

// ================= scratch (device globals) =================
__device__ float g_lambda;
__device__ float g_qkv [MROWS * 3 * DDIM];
__device__ float g_tmp1[MROWS * DDIM];
__device__ float g_h   [MROWS * DDIM];
__device__ float g_f2  [MROWS * DDIM];

// attention operands: bf16 hi/lo, [b,h,s,64] / [b,h,s,128]
#define QKELEM (BDIM*HH*SDIM*64)
__device__ __nv_bfloat16 g_q1h[QKELEM], g_q1l[QKELEM];
__device__ __nv_bfloat16 g_k1h[QKELEM], g_k1l[QKELEM];
__device__ __nv_bfloat16 g_q2h[QKELEM], g_q2l[QKELEM];
__device__ __nv_bfloat16 g_k2h[QKELEM], g_k2l[QKELEM];
__device__ __nv_bfloat16 g_vh[BDIM*HH*SDIM*128], g_vl[BDIM*HH*SDIM*128];

// bf16 hi/lo staging for GEMMs
__device__ __nv_bfloat16 g_xh[MROWS*DDIM],    g_xl[MROWS*DDIM];
__device__ __nv_bfloat16 g_wqkvTh[3*DDIM*DDIM], g_wqkvTl[3*DDIM*DDIM];
__device__ __nv_bfloat16 g_woutTh[DDIM*DDIM],   g_woutTl[DDIM*DDIM];
__device__ __nv_bfloat16 g_w1Th[4*DDIM*DDIM],   g_w1Tl[4*DDIM*DDIM];
__device__ __nv_bfloat16 g_w2Th[DDIM*4*DDIM],   g_w2Tl[DDIM*4*DDIM];
__device__ __nv_bfloat16 g_attnh[MROWS*DDIM],   g_attnl[MROWS*DDIM];
__device__ __nv_bfloat16 g_hh[MROWS*DDIM],      g_hl[MROWS*DDIM];
__device__ __nv_bfloat16 g_ff1h[MROWS*4*DDIM],  g_ff1l[MROWS*4*DDIM];

// ================= helpers =================
__device__ __forceinline__ uint32_t smem_u32(const void* p) {
    uint32_t a;
    asm("{ .reg .u64 t; cvta.to.shared.u64 t, %1; cvt.u32.u64 %0, t; }" : "=r"(a) : "l"(p));
    return a;
}
__device__ __forceinline__ void cpasync16(uint32_t dst, const void* src) {
    asm volatile("cp.async.cg.shared.global [%0], [%1], 16;" :: "r"(dst), "l"(src));
}
__device__ __forceinline__ void cp_commit() { asm volatile("cp.async.commit_group;" ::: "memory"); }
__device__ __forceinline__ void ldm4(uint32_t* r, uint32_t addr) {
    asm volatile("ldmatrix.sync.aligned.m8n8.x4.shared.b16 {%0,%1,%2,%3}, [%4];"
        : "=r"(r[0]), "=r"(r[1]), "=r"(r[2]), "=r"(r[3]) : "r"(addr));
}
__device__ __forceinline__ void ldm4t(uint32_t* r, uint32_t addr) {
    asm volatile("ldmatrix.sync.aligned.m8n8.x4.trans.shared.b16 {%0,%1,%2,%3}, [%4];"
        : "=r"(r[0]), "=r"(r[1]), "=r"(r[2]), "=r"(r[3]) : "r"(addr));
}
__device__ __forceinline__ void mma16816(float* c, const uint32_t* a, uint32_t b0, uint32_t b1) {
    asm volatile("mma.sync.aligned.m16n8k16.row.col.f32.bf16.bf16.f32 "
        "{%0,%1,%2,%3}, {%4,%5,%6,%7}, {%8,%9}, {%0,%1,%2,%3};"
        : "+f"(c[0]), "+f"(c[1]), "+f"(c[2]), "+f"(c[3])
        : "r"(a[0]), "r"(a[1]), "r"(a[2]), "r"(a[3]), "r"(b0), "r"(b1));
}
__device__ __forceinline__ uint32_t packbf(float a, float b) {
    __nv_bfloat162 t = __floats2bfloat162_rn(a, b);
    return *(uint32_t*)&t;
}

// ================= lambda =================
__global__ void lambda_kernel(const float* __restrict__ lq1, const float* __restrict__ lk1,
                              const float* __restrict__ lq2, const float* __restrict__ lk2)
{
    int lane = threadIdx.x;
    float s1 = lq1[lane]*lk1[lane] + lq1[lane+32]*lk1[lane+32];
    float s2 = lq2[lane]*lk2[lane] + lq2[lane+32]*lk2[lane+32];
#pragma unroll
    for (int o = 16; o; o >>= 1) {
        s1 += __shfl_xor_sync(0xffffffffu, s1, o);
        s2 += __shfl_xor_sync(0xffffffffu, s2, o);
    }
    if (lane == 0) g_lambda = expf(s1) - expf(s2) + LAMBDA_INIT_F;
}

// ================= bf16 hi/lo split =================
__global__ __launch_bounds__(256) void split_kernel(const float* __restrict__ in,
    __nv_bfloat16* __restrict__ oh, __nv_bfloat16* __restrict__ ol, int n4)
{
    int i = blockIdx.x * 256 + threadIdx.x;
    if (i >= n4) return;
    float4 v = ((const float4*)in)[i];
    __nv_bfloat16 h0 = __float2bfloat16(v.x), h1 = __float2bfloat16(v.y);
    __nv_bfloat16 h2 = __float2bfloat16(v.z), h3 = __float2bfloat16(v.w);
    ((__nv_bfloat162*)oh)[2*i]   = __halves2bfloat162(h0, h1);
    ((__nv_bfloat162*)oh)[2*i+1] = __halves2bfloat162(h2, h3);
    ((__nv_bfloat162*)ol)[2*i]   = __floats2bfloat162_rn(v.x - __bfloat162float(h0), v.y - __bfloat162float(h1));
    ((__nv_bfloat162*)ol)[2*i+1] = __floats2bfloat162_rn(v.z - __bfloat162float(h2), v.w - __bfloat162float(h3));
}

// ================= transpose + split: in[K,N] fp32 -> out[N,K] bf16 hi/lo =================
__global__ __launch_bounds__(256) void transpose_split_kernel(const float* __restrict__ in,
    __nv_bfloat16* __restrict__ oh, __nv_bfloat16* __restrict__ ol, int K, int N)
{
    __shared__ float t[32][33];
    const int k0 = blockIdx.y*32, n0 = blockIdx.x*32;
    const int tx = threadIdx.x, ty = threadIdx.y;
#pragma unroll
    for (int i = 0; i < 4; i++)
        t[ty + i*8][tx] = in[(size_t)(k0 + ty + i*8)*N + n0 + tx];
    __syncthreads();
#pragma unroll
    for (int i = 0; i < 4; i++) {
        int n = n0 + ty + i*8, k = k0 + tx;
        float v = t[tx][ty + i*8];
        __nv_bfloat16 hv = __float2bfloat16(v);
        oh[(size_t)n*K + k] = hv;
        ol[(size_t)n*K + k] = __float2bfloat16(v - __bfloat162float(hv));
    }
}

// ================= mma.sync bf16x3 GEMM (unchanged from R3) =================
#define TILE_B   10240
#define STAGE_B  40960
#define GEMM_SMEM (2*STAGE_B)

__global__ __launch_bounds__(256) void gemm_mma_kernel(
    const __nv_bfloat16* __restrict__ Ah, const __nv_bfloat16* __restrict__ Al,
    const __nv_bfloat16* __restrict__ Bh, const __nv_bfloat16* __restrict__ Bl,
    float* __restrict__ Cf, __nv_bfloat16* __restrict__ Ch, __nv_bfloat16* __restrict__ Cl,
    int M, int N, int K,
    const float* __restrict__ bias, const float* __restrict__ resid, int act)
{
    extern __shared__ char smem[];
    const uint32_t sb = smem_u32(smem);
    const int tid = threadIdx.x;
    const int lane = tid & 31;
    const int wid = tid >> 5;
    const int bm = blockIdx.y * 128;
    const int bn = blockIdx.x * 128;
    const int wm = wid >> 1;
    const int wn = wid & 1;

    const int lrow  = tid >> 1;
    const int lhalf = (tid & 1) * 32;
    const size_t rowB = (size_t)K * 2;
    const char* gAh = (const char*)Ah + (size_t)(bm + lrow) * rowB + lhalf;
    const char* gAl = (const char*)Al + (size_t)(bm + lrow) * rowB + lhalf;
    const char* gBh = (const char*)Bh + (size_t)(bn + lrow) * rowB + lhalf;
    const char* gBl = (const char*)Bl + (size_t)(bn + lrow) * rowB + lhalf;
    const uint32_t sdst = sb + (uint32_t)lrow * 80u + (uint32_t)lhalf;

    const int nChunks = K >> 5;

    {
        uint32_t d = sdst;
        cpasync16(d,            gAh);      cpasync16(d + 16,            gAh + 16);
        cpasync16(d + TILE_B,   gAl);      cpasync16(d + TILE_B + 16,   gAl + 16);
        cpasync16(d + 2*TILE_B, gBh);      cpasync16(d + 2*TILE_B + 16, gBh + 16);
        cpasync16(d + 3*TILE_B, gBl);      cpasync16(d + 3*TILE_B + 16, gBl + 16);
        cp_commit();
    }

    float acc[2][8][4];
#pragma unroll
    for (int i = 0; i < 2; i++)
#pragma unroll
        for (int j = 0; j < 8; j++)
#pragma unroll
            for (int k = 0; k < 4; k++) acc[i][j][k] = 0.f;

    const int lt = lane >> 3, lj = lane & 7;
    const uint32_t a_row = (uint32_t)(wm*32 + (lt & 1)*8 + lj) * 80u;
    const uint32_t a_col = (uint32_t)((lt >> 1) * 8) * 2u;
    const uint32_t b_row = (uint32_t)(wn*64 + (lt >> 1)*8 + lj) * 80u;
    const uint32_t b_col = (uint32_t)((lt & 1) * 8) * 2u;

    for (int c = 0; c < nChunks; c++) {
        if (c + 1 < nChunks) {
            const uint32_t d = sdst + (uint32_t)((c + 1) & 1) * STAGE_B;
            const size_t go = (size_t)(c + 1) * 64;
            cpasync16(d,            gAh + go);      cpasync16(d + 16,            gAh + go + 16);
            cpasync16(d + TILE_B,   gAl + go);      cpasync16(d + TILE_B + 16,   gAl + go + 16);
            cpasync16(d + 2*TILE_B, gBh + go);      cpasync16(d + 2*TILE_B + 16, gBh + go + 16);
            cpasync16(d + 3*TILE_B, gBl + go);      cpasync16(d + 3*TILE_B + 16, gBl + go + 16);
            cp_commit();
            asm volatile("cp.async.wait_group 1;" ::: "memory");
        } else {
            asm volatile("cp.async.wait_group 0;" ::: "memory");
        }
        __syncthreads();

        const uint32_t base = sb + (uint32_t)(c & 1) * STAGE_B;
#pragma unroll
        for (int ks = 0; ks < 2; ks++) {
            const uint32_t kofs = (uint32_t)ks * 32u;
            uint32_t afh[2][4], afl[2][4];
#pragma unroll
            for (int ma = 0; ma < 2; ma++) {
                ldm4(afh[ma], base +            a_row + (uint32_t)ma*16u*80u + a_col + kofs);
                ldm4(afl[ma], base + TILE_B   + a_row + (uint32_t)ma*16u*80u + a_col + kofs);
            }
            uint32_t bfh[4][4], bfl[4][4];
#pragma unroll
            for (int g = 0; g < 4; g++) {
                ldm4(bfh[g], base + 2*TILE_B + b_row + (uint32_t)g*16u*80u + b_col + kofs);
                ldm4(bfl[g], base + 3*TILE_B + b_row + (uint32_t)g*16u*80u + b_col + kofs);
            }
#pragma unroll
            for (int ma = 0; ma < 2; ma++)
#pragma unroll
                for (int g = 0; g < 4; g++)
#pragma unroll
                    for (int hf = 0; hf < 2; hf++) {
                        float* C = acc[ma][g*2 + hf];
                        mma16816(C, afh[ma], bfh[g][hf*2], bfh[g][hf*2+1]);
                        mma16816(C, afh[ma], bfl[g][hf*2], bfl[g][hf*2+1]);
                        mma16816(C, afl[ma], bfh[g][hf*2], bfh[g][hf*2+1]);
                    }
        }
        __syncthreads();
    }

#pragma unroll
    for (int ma = 0; ma < 2; ma++)
#pragma unroll
        for (int na = 0; na < 8; na++) {
            const int r0 = bm + wm*32 + ma*16 + (lane >> 2);
            const int c0 = bn + wn*64 + na*8 + 2*(lane & 3);
#pragma unroll
            for (int half = 0; half < 2; half++) {
                const int r = r0 + half*8;
                float v0 = acc[ma][na][half*2 + 0];
                float v1 = acc[ma][na][half*2 + 1];
                if (bias) { v0 += bias[c0]; v1 += bias[c0 + 1]; }
                if (act) {
                    v0 = v0 / (1.f + __expf(-v0));
                    v1 = v1 / (1.f + __expf(-v1));
                }
                const size_t o = (size_t)r * N + c0;
                if (resid) { v0 += resid[o]; v1 += resid[o + 1]; }
                if (Cf) { float2 f2o; f2o.x = v0; f2o.y = v1; *(float2*)&Cf[o] = f2o; }
                if (Ch) {
                    __nv_bfloat16 h0 = __float2bfloat16(v0);
                    __nv_bfloat16 h1 = __float2bfloat16(v1);
                    *(__nv_bfloat162*)&Ch[o] = __halves2bfloat162(h0, h1);
                    *(__nv_bfloat162*)&Cl[o] = __floats2bfloat162_rn(
                        v0 - __bfloat162float(h0), v1 - __bfloat162float(h1));
                }
            }
        }
}

// ================= RoPE + head split + q2/k2 rmsnorm + V repack (bf16 hi/lo out) ==========
__global__ __launch_bounds__(256) void rope_split_kernel(
    const float* __restrict__ sigmas, const float* __restrict__ lnq_w, const float* __restrict__ lnq_b)
{
    const int row = blockIdx.x;
    const int b = row / SDIM, s = row % SDIM;
    const float* base = g_qkv + (size_t)row * 3072;
    const int lane = threadIdx.x & 31;
    const int warp = threadIdx.x >> 5;

    for (int idx = threadIdx.x; idx < 1024; idx += 256) {
        int h = idx >> 7, e = idx & 127;
        float val = base[2048 + idx];
        size_t o = (((size_t)b*HH + h)*SDIM + s)*128 + e;
        __nv_bfloat16 hv = __float2bfloat16(val);
        g_vh[o] = hv;
        g_vl[o] = __float2bfloat16(val - __bfloat162float(hv));
    }

    int p = lane >> 1;
    float inv = (float)exp(-(double)p * 0.57564627324851148);
    float fr = (float)s * inv;
    float c0 = cosf(fr), s0 = sinf(fr);

    for (int t = warp; t < 32; t += 8) {
        const int which = t >> 4;
        const int h2 = t & 15;
        const float* src = base + which*1024 + h2*64;
        float x0 = src[lane];
        float x1 = src[lane + 32];
        float partner = src[lane ^ 1];
        float r0 = (lane & 1) ? fmaf(x0, c0,  partner * s0)
                              : fmaf(x0, c0, -partner * s0);
        const int h = h2 >> 1, comp = h2 & 1;
        size_t off = (((size_t)b*HH + h)*SDIM + s)*64;
        if (comp == 0) {
            __nv_bfloat16* dh = which ? g_k1h : g_q1h;
            __nv_bfloat16* dl = which ? g_k1l : g_q1l;
            __nv_bfloat16 h0 = __float2bfloat16(r0);
            __nv_bfloat16 h1 = __float2bfloat16(x1);
            dh[off + lane]      = h0;
            dh[off + lane + 32] = h1;
            dl[off + lane]      = __float2bfloat16(r0 - __bfloat162float(h0));
            dl[off + lane + 32] = __float2bfloat16(x1 - __bfloat162float(h1));
        } else {
            float a0 = r0 + sigmas[b*64 + lane];
            float a1 = x1 + sigmas[b*64 + lane + 32];
            float ss = a0*a0 + a1*a1;
#pragma unroll
            for (int o = 16; o; o >>= 1) ss += __shfl_xor_sync(0xffffffffu, ss, o);
            float rms = rsqrtf(ss * (1.f/64.f) + 1e-8f);
            float v0 = fmaf(a0*rms, lnq_w[lane],      lnq_b[lane]);
            float v1 = fmaf(a1*rms, lnq_w[lane+32],   lnq_b[lane+32]);
            __nv_bfloat16* dh = which ? g_k2h : g_q2h;
            __nv_bfloat16* dl = which ? g_k2l : g_q2l;
            __nv_bfloat16 h0 = __float2bfloat16(v0);
            __nv_bfloat16 h1 = __float2bfloat16(v1);
            dh[off + lane]      = h0;
            dh[off + lane + 32] = h1;
            dl[off + lane]      = __float2bfloat16(v0 - __bfloat162float(h0));
            dl[off + lane + 32] = __float2bfloat16(v1 - __bfloat162float(h1));
        }
    }
}

// ================= tensor-core dual causal attention + diff + rmsnorm(128) =================
// grid (S/64, H, B), 256 threads. Warps 0-3: branch1, warps 4-7: branch2, 16 q-rows each.
// Q tile 64x64 per branch h/l; K tile 64x64 h/l per branch; V 64x128 h/l shared.
// smem: Q (4x9216=36864) + 2 stages x (K 4x9216 + V 2x17408 = 71680) = 180224 B.
#define AKT_STRIDE 144
#define AVT_STRIDE 272
#define AQ_TILE 9216
#define AV_TILE 17408
#define AKV_STAGE 71680
#define ATT_SMEM (36864 + 2*AKV_STAGE)
#define SCALE_L2E 0.18033688011112042f   // 0.125 * log2(e)

__global__ __launch_bounds__(256) void attn_mma_kernel(
    const float* __restrict__ ln_w, const float* __restrict__ ln_b)
{
    extern __shared__ char smem[];
    const uint32_t sb = smem_u32(smem);
    const int tid = threadIdx.x, lane = tid & 31, wid = tid >> 5;
    const int br = wid >> 2, wr = wid & 3;
    const int qt = blockIdx.x, h = blockIdx.y, b = blockIdx.z;
    const int q0 = qt * 64;
    const int bh = b*HH + h;
    const size_t qkbase = (size_t)bh * SDIM * 64;
    const size_t vbase  = (size_t)bh * SDIM * 128;

    // ---- prologue: Q tiles + stage 0 K/V
    {
        const int rq = (tid >> 3), jq = tid & 7;
#pragma unroll
        for (int u = 0; u < 8; u++) {
            const int row = rq + (u & 1)*32;
            const __nv_bfloat16* src = (u < 2) ? g_q1h : (u < 4) ? g_q1l : (u < 6) ? g_q2h : g_q2l;
            cpasync16(sb + (u >> 1)*AQ_TILE + row*AKT_STRIDE + jq*16,
                      src + qkbase + (size_t)(q0 + row)*64 + jq*8);
        }
        const uint32_t kb = sb + 36864;
#pragma unroll
        for (int u = 0; u < 8; u++) {
            const int row = rq + (u & 1)*32;
            const __nv_bfloat16* src = (u < 2) ? g_k1h : (u < 4) ? g_k1l : (u < 6) ? g_k2h : g_k2l;
            cpasync16(kb + (u >> 1)*AQ_TILE + row*AKT_STRIDE + jq*16,
                      src + qkbase + (size_t)row*64 + jq*8);
        }
        const uint32_t vb = kb + 4*AQ_TILE;
        const int rv = (tid >> 4), jv = tid & 15;
#pragma unroll
        for (int u = 0; u < 8; u++) {
            const int row = rv + (u & 3)*16;
            const __nv_bfloat16* src = (u < 4) ? g_vh : g_vl;
            cpasync16(vb + (u >> 2)*AV_TILE + row*AVT_STRIDE + jv*16,
                      src + vbase + (size_t)row*128 + jv*8);
        }
        cp_commit();
    }

    // lane fragment offsets
    const int lt = lane >> 3, lj = lane & 7;
    const uint32_t qa_off = (uint32_t)(wr*16 + (lt & 1)*8 + lj)*AKT_STRIDE + (uint32_t)(lt >> 1)*16;
    const uint32_t kb_off = (uint32_t)((lt >> 1)*8 + lj)*AKT_STRIDE + (uint32_t)(lt & 1)*16;
    const uint32_t vb_off = (uint32_t)((lt & 1)*8 + lj)*AVT_STRIDE + (uint32_t)(lt >> 1)*16;
    const uint32_t qh_base = sb + br*2*AQ_TILE;
    const uint32_t ql_base = qh_base + AQ_TILE;

    float acc[16][4];
#pragma unroll
    for (int n = 0; n < 16; n++)
#pragma unroll
        for (int c = 0; c < 4; c++) acc[n][c] = 0.f;
    float m0 = -1e30f, m1 = -1e30f, l0 = 0.f, l1 = 0.f;

    const int row_l = wr*16 + (lane >> 2);     // within 64-row q tile
    const int nIter = qt + 1;

    for (int kt = 0; kt < nIter; kt++) {
        // issue next stage
        if (kt + 1 < nIter) {
            const int k0n = (kt + 1) * 64;
            const uint32_t kb = sb + 36864 + ((kt + 1) & 1)*AKV_STAGE;
            const int rq = (tid >> 3), jq = tid & 7;
#pragma unroll
            for (int u = 0; u < 8; u++) {
                const int row = rq + (u & 1)*32;
                const __nv_bfloat16* src = (u < 2) ? g_k1h : (u < 4) ? g_k1l : (u < 6) ? g_k2h : g_k2l;
                cpasync16(kb + (u >> 1)*AQ_TILE + row*AKT_STRIDE + jq*16,
                          src + qkbase + (size_t)(k0n + row)*64 + jq*8);
            }
            const uint32_t vb = kb + 4*AQ_TILE;
            const int rv = (tid >> 4), jv = tid & 15;
#pragma unroll
            for (int u = 0; u < 8; u++) {
                const int row = rv + (u & 3)*16;
                const __nv_bfloat16* src = (u < 4) ? g_vh : g_vl;
                cpasync16(vb + (u >> 2)*AV_TILE + row*AVT_STRIDE + jv*16,
                          src + vbase + (size_t)(k0n + row)*128 + jv*8);
            }
            cp_commit();
            asm volatile("cp.async.wait_group 1;" ::: "memory");
        } else {
            asm volatile("cp.async.wait_group 0;" ::: "memory");
        }
        __syncthreads();

        const uint32_t stg = sb + 36864 + (kt & 1)*AKV_STAGE;
        const uint32_t kh_base = stg + br*2*AQ_TILE;
        const uint32_t kl_base = kh_base + AQ_TILE;
        const uint32_t vh_base = stg + 4*AQ_TILE;
        const uint32_t vl_base = vh_base + AV_TILE;

        // ---- scores: S[16x64] via bf16x3 mma
        float sacc[8][4];
#pragma unroll
        for (int g = 0; g < 8; g++)
#pragma unroll
            for (int c = 0; c < 4; c++) sacc[g][c] = 0.f;
#pragma unroll
        for (int ka = 0; ka < 4; ka++) {
            uint32_t ah[4], al[4];
            ldm4(ah, qh_base + qa_off + ka*32);
            ldm4(al, ql_base + qa_off + ka*32);
#pragma unroll
            for (int g2 = 0; g2 < 4; g2++) {
                uint32_t bh4[4], bl4[4];
                ldm4(bh4, kh_base + g2*(16*AKT_STRIDE) + kb_off + ka*32);
                ldm4(bl4, kl_base + g2*(16*AKT_STRIDE) + kb_off + ka*32);
#pragma unroll
                for (int hf = 0; hf < 2; hf++) {
                    float* C = sacc[g2*2 + hf];
                    mma16816(C, ah, bh4[hf*2], bh4[hf*2+1]);
                    mma16816(C, ah, bl4[hf*2], bl4[hf*2+1]);
                    mma16816(C, al, bh4[hf*2], bh4[hf*2+1]);
                }
            }
        }

        // ---- scale (+mask on diagonal tile), online softmax
        const bool diag = (kt == qt);
        float t0 = -1e30f, t1 = -1e30f;
#pragma unroll
        for (int g = 0; g < 8; g++) {
            const int cb = g*8 + (lane & 3)*2;
#pragma unroll
            for (int c = 0; c < 4; c++) {
                float s = sacc[g][c] * SCALE_L2E;
                if (diag) {
                    const int rr = row_l + (c >= 2 ? 8 : 0);
                    const int cc = cb + (c & 1);
                    if (cc > rr) s = -1e30f;
                }
                sacc[g][c] = s;
            }
            t0 = fmaxf(t0, fmaxf(sacc[g][0], sacc[g][1]));
            t1 = fmaxf(t1, fmaxf(sacc[g][2], sacc[g][3]));
        }
        t0 = fmaxf(t0, __shfl_xor_sync(0xffffffffu, t0, 1));
        t0 = fmaxf(t0, __shfl_xor_sync(0xffffffffu, t0, 2));
        t1 = fmaxf(t1, __shfl_xor_sync(0xffffffffu, t1, 1));
        t1 = fmaxf(t1, __shfl_xor_sync(0xffffffffu, t1, 2));
        const float mn0 = fmaxf(m0, t0), mn1 = fmaxf(m1, t1);
        const float alpha0 = exp2f(m0 - mn0), alpha1 = exp2f(m1 - mn1);
        m0 = mn0; m1 = mn1;

        float rs0 = 0.f, rs1 = 0.f;
#pragma unroll
        for (int g = 0; g < 8; g++) {
            float p0 = exp2f(sacc[g][0] - mn0);
            float p1 = exp2f(sacc[g][1] - mn0);
            float p2 = exp2f(sacc[g][2] - mn1);
            float p3 = exp2f(sacc[g][3] - mn1);
            sacc[g][0] = p0; sacc[g][1] = p1; sacc[g][2] = p2; sacc[g][3] = p3;
            rs0 += p0 + p1; rs1 += p2 + p3;
        }
        rs0 += __shfl_xor_sync(0xffffffffu, rs0, 1);
        rs0 += __shfl_xor_sync(0xffffffffu, rs0, 2);
        rs1 += __shfl_xor_sync(0xffffffffu, rs1, 1);
        rs1 += __shfl_xor_sync(0xffffffffu, rs1, 2);
        l0 = l0*alpha0 + rs0;
        l1 = l1*alpha1 + rs1;

#pragma unroll
        for (int n = 0; n < 16; n++) {
            acc[n][0] *= alpha0; acc[n][1] *= alpha0;
            acc[n][2] *= alpha1; acc[n][3] *= alpha1;
        }

        // ---- P@V: split P into hi/lo fragments, 3-term mma against V h/l
#pragma unroll
        for (int ka = 0; ka < 4; ka++) {
            uint32_t ph[4], pl[4];
#pragma unroll
            for (int half = 0; half < 2; half++) {
                const int g = 2*ka + half;
                float v0 = sacc[g][0], v1 = sacc[g][1], v2 = sacc[g][2], v3 = sacc[g][3];
                __nv_bfloat16 b0 = __float2bfloat16(v0), b1v = __float2bfloat16(v1);
                __nv_bfloat16 b2 = __float2bfloat16(v2), b3 = __float2bfloat16(v3);
                __nv_bfloat162 t01 = __halves2bfloat162(b0, b1v);
                __nv_bfloat162 t23 = __halves2bfloat162(b2, b3);
                ph[half*2 + 0] = *(uint32_t*)&t01;
                ph[half*2 + 1] = *(uint32_t*)&t23;
                pl[half*2 + 0] = packbf(v0 - __bfloat162float(b0), v1 - __bfloat162float(b1v));
                pl[half*2 + 1] = packbf(v2 - __bfloat162float(b2), v3 - __bfloat162float(b3));
            }
            // reorder: a-frag = {(rl,k0),(rh,k0),(rl,k8),(rh,k8)} -> ph built as {rl/rh k0, rl/rh k8} already:
            // ph[0]=(rl,k0..),ph[1]=(rh,k0..),ph[2]=(rl,k8..),ph[3]=(rh,k8..)  OK as laid out above
#pragma unroll
            for (int np = 0; np < 8; np++) {
                uint32_t vh4[4], vl4[4];
                ldm4t(vh4, vh_base + ka*(16*AVT_STRIDE) + vb_off + np*32);
                ldm4t(vl4, vl_base + ka*(16*AVT_STRIDE) + vb_off + np*32);
#pragma unroll
                for (int hf = 0; hf < 2; hf++) {
                    float* C = acc[np*2 + hf];
                    mma16816(C, ph, vh4[hf*2], vh4[hf*2+1]);
                    mma16816(C, ph, vl4[hf*2], vl4[hf*2+1]);
                    mma16816(C, pl, vh4[hf*2], vh4[hf*2+1]);
                }
            }
        }
        __syncthreads();
    }

    // ---- epilogue: normalize, cross-branch diff, rmsnorm(128), write bf16 h/l
    const float inv0 = 1.f / l0, inv1 = 1.f / l1;
#pragma unroll
    for (int n = 0; n < 16; n++) {
        acc[n][0] *= inv0; acc[n][1] *= inv0;
        acc[n][2] *= inv1; acc[n][3] *= inv1;
    }

    float* sO = (float*)smem;
    const int rl = row_l, rh = row_l + 8;
    __syncthreads();
    if (br == 1) {
#pragma unroll
        for (int n = 0; n < 16; n++) {
            const int c = n*8 + (lane & 3)*2;
            float2 a; a.x = acc[n][0]; a.y = acc[n][1];
            float2 bvv; bvv.x = acc[n][2]; bvv.y = acc[n][3];
            *(float2*)&sO[rl*128 + c] = a;
            *(float2*)&sO[rh*128 + c] = bvv;
        }
    }
    __syncthreads();
    if (br == 0) {
        const float lam = g_lambda;
        const float osc = 1.f - LAMBDA_INIT_F;
        float ssq0 = 0.f, ssq1 = 0.f;
#pragma unroll
        for (int n = 0; n < 16; n++) {
            const int c = n*8 + (lane & 3)*2;
            float2 o2l = *(float2*)&sO[rl*128 + c];
            float2 o2h = *(float2*)&sO[rh*128 + c];
            acc[n][0] -= lam*o2l.x; acc[n][1] -= lam*o2l.y;
            acc[n][2] -= lam*o2h.x; acc[n][3] -= lam*o2h.y;
            ssq0 += acc[n][0]*acc[n][0] + acc[n][1]*acc[n][1];
            ssq1 += acc[n][2]*acc[n][2] + acc[n][3]*acc[n][3];
        }
        ssq0 += __shfl_xor_sync(0xffffffffu, ssq0, 1);
        ssq0 += __shfl_xor_sync(0xffffffffu, ssq0, 2);
        ssq1 += __shfl_xor_sync(0xffffffffu, ssq1, 1);
        ssq1 += __shfl_xor_sync(0xffffffffu, ssq1, 2);
        const float rms0 = rsqrtf(ssq0 * (1.f/128.f) + 1e-8f);
        const float rms1 = rsqrtf(ssq1 * (1.f/128.f) + 1e-8f);
        const size_t ob_l = ((size_t)(b*SDIM + q0 + rl))*DDIM + h*128;
        const size_t ob_h = ((size_t)(b*SDIM + q0 + rh))*DDIM + h*128;
#pragma unroll
        for (int n = 0; n < 16; n++) {
            const int c = n*8 + (lane & 3)*2;
            float w0 = __ldg(&ln_w[c]), w1 = __ldg(&ln_w[c+1]);
            float bb0 = __ldg(&ln_b[c]), bb1 = __ldg(&ln_b[c+1]);
            float v0 = (acc[n][0]*rms0*w0 + bb0) * osc;
            float v1 = (acc[n][1]*rms0*w1 + bb1) * osc;
            float v2 = (acc[n][2]*rms1*w0 + bb0) * osc;
            float v3 = (acc[n][3]*rms1*w1 + bb1) * osc;
            __nv_bfloat16 h0 = __float2bfloat16(v0), h1v = __float2bfloat16(v1);
            __nv_bfloat16 h2 = __float2bfloat16(v2), h3 = __float2bfloat16(v3);
            *(__nv_bfloat162*)&g_attnh[ob_l + c] = __halves2bfloat162(h0, h1v);
            *(__nv_bfloat162*)&g_attnl[ob_l + c] = __floats2bfloat162_rn(
                v0 - __bfloat162float(h0), v1 - __bfloat162float(h1v));
            *(__nv_bfloat162*)&g_attnh[ob_h + c] = __halves2bfloat162(h2, h3);
            *(__nv_bfloat162*)&g_attnl[ob_h + c] = __floats2bfloat162_rn(
                v2 - __bfloat162float(h2), v3 - __bfloat162float(h3));
        }
    }
}

// ================= layernorm over 1024 (+ optional bf16 split out) =================
__global__ __launch_bounds__(256) void layernorm_kernel(
    const float* __restrict__ in, const float* __restrict__ w, const float* __restrict__ bb,
    float* __restrict__ out, __nv_bfloat16* __restrict__ oh, __nv_bfloat16* __restrict__ ol)
{
    __shared__ float red1[8], red2[8];
    const int row = blockIdx.x;
    const float* x = in + (size_t)row * DDIM;
    float v[4];
    float s = 0.f, s2 = 0.f;
#pragma unroll
    for (int it = 0; it < 4; it++) {
        float t = x[threadIdx.x + it*256];
        v[it] = t; s += t; s2 += t*t;
    }
#pragma unroll
    for (int o = 16; o; o >>= 1) {
        s  += __shfl_xor_sync(0xffffffffu, s,  o);
        s2 += __shfl_xor_sync(0xffffffffu, s2, o);
    }
    const int lane = threadIdx.x & 31, wp = threadIdx.x >> 5;
    if (lane == 0) { red1[wp] = s; red2[wp] = s2; }
    __syncthreads();
    if (wp == 0) {
        s  = (lane < 8) ? red1[lane] : 0.f;
        s2 = (lane < 8) ? red2[lane] : 0.f;
#pragma unroll
        for (int o = 4; o; o >>= 1) {
            s  += __shfl_xor_sync(0xffffffffu, s,  o);
            s2 += __shfl_xor_sync(0xffffffffu, s2, o);
        }
        if (lane == 0) { red1[0] = s * (1.f/1024.f); red2[0] = s2 * (1.f/1024.f); }
    }
    __syncthreads();
    const float mean = red1[0];
    const float var = red2[0] - mean*mean;
    const float rstd = rsqrtf(var + 1e-5f);
#pragma unroll
    for (int it = 0; it < 4; it++) {
        int c = threadIdx.x + it*256;
        size_t idx = (size_t)row*DDIM + c;
        float y = (v[it] - mean)*rstd*w[c] + bb[c];
        out[idx] = y;
        if (oh) {
            __nv_bfloat16 hv = __float2bfloat16(y);
            oh[idx] = hv;
            ol[idx] = __float2bfloat16(y - __bfloat162float(hv));
        }
    }
}

// ================= launch =================
extern "C" void kernel_launch(void* const* d_in, const int* in_sizes, int n_in,
                              void* d_out, int out_size)
{
    (void)in_sizes; (void)n_in; (void)out_size;
    const float* x      = (const float*)d_in[0];
    const float* sigmas = (const float*)d_in[1];
    const float* w_qkv  = (const float*)d_in[2];
    const float* w_out  = (const float*)d_in[3];
    const float* lq1    = (const float*)d_in[4];
    const float* lk1    = (const float*)d_in[5];
    const float* lq2    = (const float*)d_in[6];
    const float* lk2    = (const float*)d_in[7];
    const float* ln_w   = (const float*)d_in[8];
    const float* ln_b   = (const float*)d_in[9];
    const float* lnq_w  = (const float*)d_in[10];
    const float* lnq_b  = (const float*)d_in[11];
    const float* ln1_w  = (const float*)d_in[12];
    const float* ln1_b  = (const float*)d_in[13];
    const float* ln2_w  = (const float*)d_in[14];
    const float* ln2_b  = (const float*)d_in[15];
    const float* w1     = (const float*)d_in[16];
    const float* b1     = (const float*)d_in[17];
    const float* w2     = (const float*)d_in[18];
    const float* b2     = (const float*)d_in[19];
    float* out = (float*)d_out;

    void *p_qkv, *p_tmp1, *p_h, *p_f2;
    void *p_xh, *p_xl, *p_wqkvTh, *p_wqkvTl, *p_woutTh, *p_woutTl;
    void *p_w1Th, *p_w1Tl, *p_w2Th, *p_w2Tl;
    void *p_attnh, *p_attnl, *p_hh, *p_hl, *p_ff1h, *p_ff1l;
    cudaGetSymbolAddress(&p_qkv,  g_qkv);
    cudaGetSymbolAddress(&p_tmp1, g_tmp1);
    cudaGetSymbolAddress(&p_h,    g_h);
    cudaGetSymbolAddress(&p_f2,   g_f2);
    cudaGetSymbolAddress(&p_xh, g_xh);       cudaGetSymbolAddress(&p_xl, g_xl);
    cudaGetSymbolAddress(&p_wqkvTh, g_wqkvTh); cudaGetSymbolAddress(&p_wqkvTl, g_wqkvTl);
    cudaGetSymbolAddress(&p_woutTh, g_woutTh); cudaGetSymbolAddress(&p_woutTl, g_woutTl);
    cudaGetSymbolAddress(&p_w1Th, g_w1Th);   cudaGetSymbolAddress(&p_w1Tl, g_w1Tl);
    cudaGetSymbolAddress(&p_w2Th, g_w2Th);   cudaGetSymbolAddress(&p_w2Tl, g_w2Tl);
    cudaGetSymbolAddress(&p_attnh, g_attnh); cudaGetSymbolAddress(&p_attnl, g_attnl);
    cudaGetSymbolAddress(&p_hh, g_hh);       cudaGetSymbolAddress(&p_hl, g_hl);
    cudaGetSymbolAddress(&p_ff1h, g_ff1h);   cudaGetSymbolAddress(&p_ff1l, g_ff1l);

    cudaFuncSetAttribute(gemm_mma_kernel, cudaFuncAttributeMaxDynamicSharedMemorySize, GEMM_SMEM);
    cudaFuncSetAttribute(attn_mma_kernel, cudaFuncAttributeMaxDynamicSharedMemorySize, ATT_SMEM);

    lambda_kernel<<<1, 32>>>(lq1, lk1, lq2, lk2);

    split_kernel<<<(MROWS*DDIM/4 + 255)/256, 256>>>(x, (__nv_bfloat16*)p_xh, (__nv_bfloat16*)p_xl, MROWS*DDIM/4);
    transpose_split_kernel<<<dim3(3072/32, 1024/32), dim3(32,8)>>>(w_qkv, (__nv_bfloat16*)p_wqkvTh, (__nv_bfloat16*)p_wqkvTl, 1024, 3072);
    transpose_split_kernel<<<dim3(1024/32, 1024/32), dim3(32,8)>>>(w_out, (__nv_bfloat16*)p_woutTh, (__nv_bfloat16*)p_woutTl, 1024, 1024);
    transpose_split_kernel<<<dim3(4096/32, 1024/32), dim3(32,8)>>>(w1, (__nv_bfloat16*)p_w1Th, (__nv_bfloat16*)p_w1Tl, 1024, 4096);
    transpose_split_kernel<<<dim3(1024/32, 4096/32), dim3(32,8)>>>(w2, (__nv_bfloat16*)p_w2Th, (__nv_bfloat16*)p_w2Tl, 4096, 1024);

    // qkv = x @ w_qkv
    gemm_mma_kernel<<<dim3(3072/128, 4096/128), 256, GEMM_SMEM>>>(
        (const __nv_bfloat16*)p_xh, (const __nv_bfloat16*)p_xl,
        (const __nv_bfloat16*)p_wqkvTh, (const __nv_bfloat16*)p_wqkvTl,
        (float*)p_qkv, nullptr, nullptr, MROWS, 3072, 1024, nullptr, nullptr, 0);

    rope_split_kernel<<<MROWS, 256>>>(sigmas, lnq_w, lnq_b);

    attn_mma_kernel<<<dim3(SDIM/64, HH, BDIM), 256, ATT_SMEM>>>(ln_w, ln_b);

    // tmp1 = attn @ w_out + x
    gemm_mma_kernel<<<dim3(1024/128, 4096/128), 256, GEMM_SMEM>>>(
        (const __nv_bfloat16*)p_attnh, (const __nv_bfloat16*)p_attnl,
        (const __nv_bfloat16*)p_woutTh, (const __nv_bfloat16*)p_woutTl,
        (float*)p_tmp1, nullptr, nullptr, MROWS, 1024, 1024, nullptr, x, 0);

    layernorm_kernel<<<MROWS, 256>>>((const float*)p_tmp1, ln1_w, ln1_b,
        (float*)p_h, (__nv_bfloat16*)p_hh, (__nv_bfloat16*)p_hl);

    // ff1 = silu(h @ w1 + b1)
    gemm_mma_kernel<<<dim3(4096/128, 4096/128), 256, GEMM_SMEM>>>(
        (const __nv_bfloat16*)p_hh, (const __nv_bfloat16*)p_hl,
        (const __nv_bfloat16*)p_w1Th, (const __nv_bfloat16*)p_w1Tl,
        nullptr, (__nv_bfloat16*)p_ff1h, (__nv_bfloat16*)p_ff1l, MROWS, 4096, 1024, b1, nullptr, 1);

    // f2 = ff1 @ w2 + b2 + h
    gemm_mma_kernel<<<dim3(1024/128, 4096/128), 256, GEMM_SMEM>>>(
        (const __nv_bfloat16*)p_ff1h, (const __nv_bfloat16*)p_ff1l,
        (const __nv_bfloat16*)p_w2Th, (const __nv_bfloat16*)p_w2Tl,
        (float*)p_f2, nullptr, nullptr, MROWS, 1024, 4096, b2, (const float*)p_h, 0);

    layernorm_kernel<<<MROWS, 256>>>((const float*)p_f2, ln2_w, ln2_b, out, nullptr, nullptr);
}

// round 6
// speedup vs baseline: 2.6225x; 1.0475x over previous
#include <cuda_runtime.h>
#include <cuda_bf16.h>
#include <cuda_fp16.h>
#include <math.h>
#include <stdint.h>

// Problem constants
#define BDIM 2
#define SDIM 2048
#define DDIM 1024
#define HH   8
#define MROWS (BDIM*SDIM)          // 4096
static __device__ __constant__ float LAMBDA_INIT_F = 0.470713018343584f; // 0.8 - 0.6*exp(-0.6)

// ================= scratch (device globals) =================
__device__ float g_lambda;
__device__ float g_qkv [MROWS * 3 * DDIM];
__device__ float g_tmp1[MROWS * DDIM];
__device__ float g_h   [MROWS * DDIM];
__device__ float g_f2  [MROWS * DDIM];

// attention operands: bf16 hi/lo, [b,h,s,64] / [b,h,s,128]
#define QKELEM (BDIM*HH*SDIM*64)
__device__ __nv_bfloat16 g_q1h[QKELEM], g_q1l[QKELEM];
__device__ __nv_bfloat16 g_k1h[QKELEM], g_k1l[QKELEM];
__device__ __nv_bfloat16 g_q2h[QKELEM], g_q2l[QKELEM];
__device__ __nv_bfloat16 g_k2h[QKELEM], g_k2l[QKELEM];
__device__ __nv_bfloat16 g_vh[BDIM*HH*SDIM*128], g_vl[BDIM*HH*SDIM*128];

// bf16 hi/lo staging for bf16x3 GEMMs (qkv, wout)
__device__ __nv_bfloat16 g_xh[MROWS*DDIM],    g_xl[MROWS*DDIM];
__device__ __nv_bfloat16 g_wqkvTh[3*DDIM*DDIM], g_wqkvTl[3*DDIM*DDIM];
__device__ __nv_bfloat16 g_woutTh[DDIM*DDIM],   g_woutTl[DDIM*DDIM];
__device__ __nv_bfloat16 g_attnh[MROWS*DDIM],   g_attnl[MROWS*DDIM];

// fp16 staging for 2-term GEMMs (ff1, ff2). Weights scaled x64, activations /64.
__device__ __half g_h16  [MROWS*DDIM];
__device__ __half g_ff116[MROWS*4*DDIM];
__device__ __half g_w1T16h[4*DDIM*DDIM], g_w1T16l[4*DDIM*DDIM];   // [4096,1024]
__device__ __half g_w2T16h[DDIM*4*DDIM], g_w2T16l[DDIM*4*DDIM];   // [1024,4096]

// ================= helpers =================
__device__ __forceinline__ uint32_t smem_u32(const void* p) {
    uint32_t a;
    asm("{ .reg .u64 t; cvta.to.shared.u64 t, %1; cvt.u32.u64 %0, t; }" : "=r"(a) : "l"(p));
    return a;
}
__device__ __forceinline__ void cpasync16(uint32_t dst, const void* src) {
    asm volatile("cp.async.cg.shared.global [%0], [%1], 16;" :: "r"(dst), "l"(src));
}
__device__ __forceinline__ void cp_commit() { asm volatile("cp.async.commit_group;" ::: "memory"); }
__device__ __forceinline__ void ldm4(uint32_t* r, uint32_t addr) {
    asm volatile("ldmatrix.sync.aligned.m8n8.x4.shared.b16 {%0,%1,%2,%3}, [%4];"
        : "=r"(r[0]), "=r"(r[1]), "=r"(r[2]), "=r"(r[3]) : "r"(addr));
}
__device__ __forceinline__ void ldm4t(uint32_t* r, uint32_t addr) {
    asm volatile("ldmatrix.sync.aligned.m8n8.x4.trans.shared.b16 {%0,%1,%2,%3}, [%4];"
        : "=r"(r[0]), "=r"(r[1]), "=r"(r[2]), "=r"(r[3]) : "r"(addr));
}
__device__ __forceinline__ void mma16816(float* c, const uint32_t* a, uint32_t b0, uint32_t b1) {
    asm volatile("mma.sync.aligned.m16n8k16.row.col.f32.bf16.bf16.f32 "
        "{%0,%1,%2,%3}, {%4,%5,%6,%7}, {%8,%9}, {%0,%1,%2,%3};"
        : "+f"(c[0]), "+f"(c[1]), "+f"(c[2]), "+f"(c[3])
        : "r"(a[0]), "r"(a[1]), "r"(a[2]), "r"(a[3]), "r"(b0), "r"(b1));
}
__device__ __forceinline__ void mma16816h(float* c, const uint32_t* a, uint32_t b0, uint32_t b1) {
    asm volatile("mma.sync.aligned.m16n8k16.row.col.f32.f16.f16.f32 "
        "{%0,%1,%2,%3}, {%4,%5,%6,%7}, {%8,%9}, {%0,%1,%2,%3};"
        : "+f"(c[0]), "+f"(c[1]), "+f"(c[2]), "+f"(c[3])
        : "r"(a[0]), "r"(a[1]), "r"(a[2]), "r"(a[3]), "r"(b0), "r"(b1));
}
__device__ __forceinline__ uint32_t packbf(float a, float b) {
    __nv_bfloat162 t = __floats2bfloat162_rn(a, b);
    return *(uint32_t*)&t;
}

// ================= lambda =================
__global__ void lambda_kernel(const float* __restrict__ lq1, const float* __restrict__ lk1,
                              const float* __restrict__ lq2, const float* __restrict__ lk2)
{
    int lane = threadIdx.x;
    float s1 = lq1[lane]*lk1[lane] + lq1[lane+32]*lk1[lane+32];
    float s2 = lq2[lane]*lk2[lane] + lq2[lane+32]*lk2[lane+32];
#pragma unroll
    for (int o = 16; o; o >>= 1) {
        s1 += __shfl_xor_sync(0xffffffffu, s1, o);
        s2 += __shfl_xor_sync(0xffffffffu, s2, o);
    }
    if (lane == 0) g_lambda = expf(s1) - expf(s2) + LAMBDA_INIT_F;
}

// ================= bf16 hi/lo split =================
__global__ __launch_bounds__(256) void split_kernel(const float* __restrict__ in,
    __nv_bfloat16* __restrict__ oh, __nv_bfloat16* __restrict__ ol, int n4)
{
    int i = blockIdx.x * 256 + threadIdx.x;
    if (i >= n4) return;
    float4 v = ((const float4*)in)[i];
    __nv_bfloat16 h0 = __float2bfloat16(v.x), h1 = __float2bfloat16(v.y);
    __nv_bfloat16 h2 = __float2bfloat16(v.z), h3 = __float2bfloat16(v.w);
    ((__nv_bfloat162*)oh)[2*i]   = __halves2bfloat162(h0, h1);
    ((__nv_bfloat162*)oh)[2*i+1] = __halves2bfloat162(h2, h3);
    ((__nv_bfloat162*)ol)[2*i]   = __floats2bfloat162_rn(v.x - __bfloat162float(h0), v.y - __bfloat162float(h1));
    ((__nv_bfloat162*)ol)[2*i+1] = __floats2bfloat162_rn(v.z - __bfloat162float(h2), v.w - __bfloat162float(h3));
}

// ================= transpose + split bf16: in[K,N] fp32 -> out[N,K] bf16 hi/lo =================
__global__ __launch_bounds__(256) void transpose_split_kernel(const float* __restrict__ in,
    __nv_bfloat16* __restrict__ oh, __nv_bfloat16* __restrict__ ol, int K, int N)
{
    __shared__ float t[32][33];
    const int k0 = blockIdx.y*32, n0 = blockIdx.x*32;
    const int tx = threadIdx.x, ty = threadIdx.y;
#pragma unroll
    for (int i = 0; i < 4; i++)
        t[ty + i*8][tx] = in[(size_t)(k0 + ty + i*8)*N + n0 + tx];
    __syncthreads();
#pragma unroll
    for (int i = 0; i < 4; i++) {
        int n = n0 + ty + i*8, k = k0 + tx;
        float v = t[tx][ty + i*8];
        __nv_bfloat16 hv = __float2bfloat16(v);
        oh[(size_t)n*K + k] = hv;
        ol[(size_t)n*K + k] = __float2bfloat16(v - __bfloat162float(hv));
    }
}

// ================= transpose + split fp16 x64: in[K,N] fp32 -> out[N,K] fp16 hi/lo (scaled x64) ==
__global__ __launch_bounds__(256) void transpose_split_f16_kernel(const float* __restrict__ in,
    __half* __restrict__ oh, __half* __restrict__ ol, int K, int N)
{
    __shared__ float t[32][33];
    const int k0 = blockIdx.y*32, n0 = blockIdx.x*32;
    const int tx = threadIdx.x, ty = threadIdx.y;
#pragma unroll
    for (int i = 0; i < 4; i++)
        t[ty + i*8][tx] = in[(size_t)(k0 + ty + i*8)*N + n0 + tx];
    __syncthreads();
#pragma unroll
    for (int i = 0; i < 4; i++) {
        int n = n0 + ty + i*8, k = k0 + tx;
        float v = t[tx][ty + i*8] * 64.f;
        __half hv = __float2half(v);
        oh[(size_t)n*K + k] = hv;
        ol[(size_t)n*K + k] = __float2half(v - __half2float(hv));
    }
}

// ================= mma.sync bf16x3 GEMM (qkv, wout) =================
#define TILE_B   10240
#define STAGE_B  40960
#define GEMM_SMEM (2*STAGE_B)

__global__ __launch_bounds__(256) void gemm_mma_kernel(
    const __nv_bfloat16* __restrict__ Ah, const __nv_bfloat16* __restrict__ Al,
    const __nv_bfloat16* __restrict__ Bh, const __nv_bfloat16* __restrict__ Bl,
    float* __restrict__ Cf,
    int M, int N, int K,
    const float* __restrict__ bias, const float* __restrict__ resid, int act)
{
    extern __shared__ char smem[];
    const uint32_t sb = smem_u32(smem);
    const int tid = threadIdx.x;
    const int lane = tid & 31;
    const int wid = tid >> 5;
    const int bm = blockIdx.y * 128;
    const int bn = blockIdx.x * 128;
    const int wm = wid >> 1;
    const int wn = wid & 1;

    const int lrow  = tid >> 1;
    const int lhalf = (tid & 1) * 32;
    const size_t rowB = (size_t)K * 2;
    const char* gAh = (const char*)Ah + (size_t)(bm + lrow) * rowB + lhalf;
    const char* gAl = (const char*)Al + (size_t)(bm + lrow) * rowB + lhalf;
    const char* gBh = (const char*)Bh + (size_t)(bn + lrow) * rowB + lhalf;
    const char* gBl = (const char*)Bl + (size_t)(bn + lrow) * rowB + lhalf;
    const uint32_t sdst = sb + (uint32_t)lrow * 80u + (uint32_t)lhalf;

    const int nChunks = K >> 5;

    {
        uint32_t d = sdst;
        cpasync16(d,            gAh);      cpasync16(d + 16,            gAh + 16);
        cpasync16(d + TILE_B,   gAl);      cpasync16(d + TILE_B + 16,   gAl + 16);
        cpasync16(d + 2*TILE_B, gBh);      cpasync16(d + 2*TILE_B + 16, gBh + 16);
        cpasync16(d + 3*TILE_B, gBl);      cpasync16(d + 3*TILE_B + 16, gBl + 16);
        cp_commit();
    }

    float acc[2][8][4];
#pragma unroll
    for (int i = 0; i < 2; i++)
#pragma unroll
        for (int j = 0; j < 8; j++)
#pragma unroll
            for (int k = 0; k < 4; k++) acc[i][j][k] = 0.f;

    const int lt = lane >> 3, lj = lane & 7;
    const uint32_t a_row = (uint32_t)(wm*32 + (lt & 1)*8 + lj) * 80u;
    const uint32_t a_col = (uint32_t)((lt >> 1) * 8) * 2u;
    const uint32_t b_row = (uint32_t)(wn*64 + (lt >> 1)*8 + lj) * 80u;
    const uint32_t b_col = (uint32_t)((lt & 1) * 8) * 2u;

    for (int c = 0; c < nChunks; c++) {
        if (c + 1 < nChunks) {
            const uint32_t d = sdst + (uint32_t)((c + 1) & 1) * STAGE_B;
            const size_t go = (size_t)(c + 1) * 64;
            cpasync16(d,            gAh + go);      cpasync16(d + 16,            gAh + go + 16);
            cpasync16(d + TILE_B,   gAl + go);      cpasync16(d + TILE_B + 16,   gAl + go + 16);
            cpasync16(d + 2*TILE_B, gBh + go);      cpasync16(d + 2*TILE_B + 16, gBh + go + 16);
            cpasync16(d + 3*TILE_B, gBl + go);      cpasync16(d + 3*TILE_B + 16, gBl + go + 16);
            cp_commit();
            asm volatile("cp.async.wait_group 1;" ::: "memory");
        } else {
            asm volatile("cp.async.wait_group 0;" ::: "memory");
        }
        __syncthreads();

        const uint32_t base = sb + (uint32_t)(c & 1) * STAGE_B;
#pragma unroll
        for (int ks = 0; ks < 2; ks++) {
            const uint32_t kofs = (uint32_t)ks * 32u;
            uint32_t afh[2][4], afl[2][4];
#pragma unroll
            for (int ma = 0; ma < 2; ma++) {
                ldm4(afh[ma], base +            a_row + (uint32_t)ma*16u*80u + a_col + kofs);
                ldm4(afl[ma], base + TILE_B   + a_row + (uint32_t)ma*16u*80u + a_col + kofs);
            }
            uint32_t bfh[4][4], bfl[4][4];
#pragma unroll
            for (int g = 0; g < 4; g++) {
                ldm4(bfh[g], base + 2*TILE_B + b_row + (uint32_t)g*16u*80u + b_col + kofs);
                ldm4(bfl[g], base + 3*TILE_B + b_row + (uint32_t)g*16u*80u + b_col + kofs);
            }
#pragma unroll
            for (int ma = 0; ma < 2; ma++)
#pragma unroll
                for (int g = 0; g < 4; g++)
#pragma unroll
                    for (int hf = 0; hf < 2; hf++) {
                        float* C = acc[ma][g*2 + hf];
                        mma16816(C, afh[ma], bfh[g][hf*2], bfh[g][hf*2+1]);
                        mma16816(C, afh[ma], bfl[g][hf*2], bfl[g][hf*2+1]);
                        mma16816(C, afl[ma], bfh[g][hf*2], bfh[g][hf*2+1]);
                    }
        }
        __syncthreads();
    }

#pragma unroll
    for (int ma = 0; ma < 2; ma++)
#pragma unroll
        for (int na = 0; na < 8; na++) {
            const int r0 = bm + wm*32 + ma*16 + (lane >> 2);
            const int c0 = bn + wn*64 + na*8 + 2*(lane & 3);
#pragma unroll
            for (int half = 0; half < 2; half++) {
                const int r = r0 + half*8;
                float v0 = acc[ma][na][half*2 + 0];
                float v1 = acc[ma][na][half*2 + 1];
                if (bias) { v0 += bias[c0]; v1 += bias[c0 + 1]; }
                if (act) {
                    v0 = v0 / (1.f + __expf(-v0));
                    v1 = v1 / (1.f + __expf(-v1));
                }
                const size_t o = (size_t)r * N + c0;
                if (resid) { v0 += resid[o]; v1 += resid[o + 1]; }
                float2 f2o; f2o.x = v0; f2o.y = v1;
                *(float2*)&Cf[o] = f2o;
            }
        }
}

// ================= mma.sync fp16 2-term GEMM (ff1, ff2) =================
// C[M,N] = Ah[M,K] @ (Bh+Bl)[N,K]^T, fp32 accum. A single fp16 (scaled /64),
// B fp16 hi/lo (scaled x64). Product scales cancel exactly.
#define F_TILE_B  10240
#define F_STAGE_B 30720
#define GEMMF_SMEM (2*F_STAGE_B)

__global__ __launch_bounds__(256) void gemm_f16_kernel(
    const __half* __restrict__ Ah,
    const __half* __restrict__ Bh, const __half* __restrict__ Bl,
    float* __restrict__ Cf, __half* __restrict__ Ch16,
    int M, int N, int K,
    const float* __restrict__ bias, const float* __restrict__ resid, int act)
{
    extern __shared__ char smem[];
    const uint32_t sb = smem_u32(smem);
    const int tid = threadIdx.x;
    const int lane = tid & 31;
    const int wid = tid >> 5;
    const int bm = blockIdx.y * 128;
    const int bn = blockIdx.x * 128;
    const int wm = wid >> 1;
    const int wn = wid & 1;

    const int lrow  = tid >> 1;
    const int lhalf = (tid & 1) * 32;
    const size_t rowB = (size_t)K * 2;
    const char* gA  = (const char*)Ah + (size_t)(bm + lrow) * rowB + lhalf;
    const char* gBh = (const char*)Bh + (size_t)(bn + lrow) * rowB + lhalf;
    const char* gBl = (const char*)Bl + (size_t)(bn + lrow) * rowB + lhalf;
    const uint32_t sdst = sb + (uint32_t)lrow * 80u + (uint32_t)lhalf;

    const int nChunks = K >> 5;

    {
        uint32_t d = sdst;
        cpasync16(d,             gA);       cpasync16(d + 16,             gA + 16);
        cpasync16(d + F_TILE_B,  gBh);      cpasync16(d + F_TILE_B + 16,  gBh + 16);
        cpasync16(d + 2*F_TILE_B, gBl);     cpasync16(d + 2*F_TILE_B + 16, gBl + 16);
        cp_commit();
    }

    float acc[2][8][4];
#pragma unroll
    for (int i = 0; i < 2; i++)
#pragma unroll
        for (int j = 0; j < 8; j++)
#pragma unroll
            for (int k = 0; k < 4; k++) acc[i][j][k] = 0.f;

    const int lt = lane >> 3, lj = lane & 7;
    const uint32_t a_row = (uint32_t)(wm*32 + (lt & 1)*8 + lj) * 80u;
    const uint32_t a_col = (uint32_t)((lt >> 1) * 8) * 2u;
    const uint32_t b_row = (uint32_t)(wn*64 + (lt >> 1)*8 + lj) * 80u;
    const uint32_t b_col = (uint32_t)((lt & 1) * 8) * 2u;

    for (int c = 0; c < nChunks; c++) {
        if (c + 1 < nChunks) {
            const uint32_t d = sdst + (uint32_t)((c + 1) & 1) * F_STAGE_B;
            const size_t go = (size_t)(c + 1) * 64;
            cpasync16(d,              gA + go);   cpasync16(d + 16,              gA + go + 16);
            cpasync16(d + F_TILE_B,   gBh + go);  cpasync16(d + F_TILE_B + 16,   gBh + go + 16);
            cpasync16(d + 2*F_TILE_B, gBl + go);  cpasync16(d + 2*F_TILE_B + 16, gBl + go + 16);
            cp_commit();
            asm volatile("cp.async.wait_group 1;" ::: "memory");
        } else {
            asm volatile("cp.async.wait_group 0;" ::: "memory");
        }
        __syncthreads();

        const uint32_t base = sb + (uint32_t)(c & 1) * F_STAGE_B;
#pragma unroll
        for (int ks = 0; ks < 2; ks++) {
            const uint32_t kofs = (uint32_t)ks * 32u;
            uint32_t af[2][4];
#pragma unroll
            for (int ma = 0; ma < 2; ma++)
                ldm4(af[ma], base + a_row + (uint32_t)ma*16u*80u + a_col + kofs);
            uint32_t bfh[4][4], bfl[4][4];
#pragma unroll
            for (int g = 0; g < 4; g++) {
                ldm4(bfh[g], base + F_TILE_B   + b_row + (uint32_t)g*16u*80u + b_col + kofs);
                ldm4(bfl[g], base + 2*F_TILE_B + b_row + (uint32_t)g*16u*80u + b_col + kofs);
            }
#pragma unroll
            for (int ma = 0; ma < 2; ma++)
#pragma unroll
                for (int g = 0; g < 4; g++)
#pragma unroll
                    for (int hf = 0; hf < 2; hf++) {
                        float* C = acc[ma][g*2 + hf];
                        mma16816h(C, af[ma], bfh[g][hf*2], bfh[g][hf*2+1]);
                        mma16816h(C, af[ma], bfl[g][hf*2], bfl[g][hf*2+1]);
                    }
        }
        __syncthreads();
    }

#pragma unroll
    for (int ma = 0; ma < 2; ma++)
#pragma unroll
        for (int na = 0; na < 8; na++) {
            const int r0 = bm + wm*32 + ma*16 + (lane >> 2);
            const int c0 = bn + wn*64 + na*8 + 2*(lane & 3);
#pragma unroll
            for (int half = 0; half < 2; half++) {
                const int r = r0 + half*8;
                float v0 = acc[ma][na][half*2 + 0];
                float v1 = acc[ma][na][half*2 + 1];
                if (bias) { v0 += bias[c0]; v1 += bias[c0 + 1]; }
                if (act) {
                    v0 = v0 / (1.f + __expf(-v0));
                    v1 = v1 / (1.f + __expf(-v1));
                }
                const size_t o = (size_t)r * N + c0;
                if (resid) { v0 += resid[o]; v1 += resid[o + 1]; }
                if (Cf) { float2 f2o; f2o.x = v0; f2o.y = v1; *(float2*)&Cf[o] = f2o; }
                if (Ch16) {
                    __half2 hv = __floats2half2_rn(v0 * 0.015625f, v1 * 0.015625f);
                    *(__half2*)&Ch16[o] = hv;
                }
            }
        }
}

// ================= RoPE + head split + q2/k2 rmsnorm + V repack (bf16 hi/lo out) ==========
__global__ __launch_bounds__(256) void rope_split_kernel(
    const float* __restrict__ sigmas, const float* __restrict__ lnq_w, const float* __restrict__ lnq_b)
{
    const int row = blockIdx.x;
    const int b = row / SDIM, s = row % SDIM;
    const float* base = g_qkv + (size_t)row * 3072;
    const int lane = threadIdx.x & 31;
    const int warp = threadIdx.x >> 5;

    for (int idx = threadIdx.x; idx < 1024; idx += 256) {
        int h = idx >> 7, e = idx & 127;
        float val = base[2048 + idx];
        size_t o = (((size_t)b*HH + h)*SDIM + s)*128 + e;
        __nv_bfloat16 hv = __float2bfloat16(val);
        g_vh[o] = hv;
        g_vl[o] = __float2bfloat16(val - __bfloat162float(hv));
    }

    int p = lane >> 1;
    float inv = (float)exp(-(double)p * 0.57564627324851148);
    float fr = (float)s * inv;
    float c0 = cosf(fr), s0 = sinf(fr);

    for (int t = warp; t < 32; t += 8) {
        const int which = t >> 4;
        const int h2 = t & 15;
        const float* src = base + which*1024 + h2*64;
        float x0 = src[lane];
        float x1 = src[lane + 32];
        float partner = src[lane ^ 1];
        float r0 = (lane & 1) ? fmaf(x0, c0,  partner * s0)
                              : fmaf(x0, c0, -partner * s0);
        const int h = h2 >> 1, comp = h2 & 1;
        size_t off = (((size_t)b*HH + h)*SDIM + s)*64;
        if (comp == 0) {
            __nv_bfloat16* dh = which ? g_k1h : g_q1h;
            __nv_bfloat16* dl = which ? g_k1l : g_q1l;
            __nv_bfloat16 h0 = __float2bfloat16(r0);
            __nv_bfloat16 h1 = __float2bfloat16(x1);
            dh[off + lane]      = h0;
            dh[off + lane + 32] = h1;
            dl[off + lane]      = __float2bfloat16(r0 - __bfloat162float(h0));
            dl[off + lane + 32] = __float2bfloat16(x1 - __bfloat162float(h1));
        } else {
            float a0 = r0 + sigmas[b*64 + lane];
            float a1 = x1 + sigmas[b*64 + lane + 32];
            float ss = a0*a0 + a1*a1;
#pragma unroll
            for (int o = 16; o; o >>= 1) ss += __shfl_xor_sync(0xffffffffu, ss, o);
            float rms = rsqrtf(ss * (1.f/64.f) + 1e-8f);
            float v0 = fmaf(a0*rms, lnq_w[lane],      lnq_b[lane]);
            float v1 = fmaf(a1*rms, lnq_w[lane+32],   lnq_b[lane+32]);
            __nv_bfloat16* dh = which ? g_k2h : g_q2h;
            __nv_bfloat16* dl = which ? g_k2l : g_q2l;
            __nv_bfloat16 h0 = __float2bfloat16(v0);
            __nv_bfloat16 h1 = __float2bfloat16(v1);
            dh[off + lane]      = h0;
            dh[off + lane + 32] = h1;
            dl[off + lane]      = __float2bfloat16(v0 - __bfloat162float(h0));
            dl[off + lane + 32] = __float2bfloat16(v1 - __bfloat162float(h1));
        }
    }
}

// ================= tensor-core dual causal attention + diff + rmsnorm(128) =================
#define AKT_STRIDE 144
#define AVT_STRIDE 272
#define AQ_TILE 9216
#define AV_TILE 17408
#define AKV_STAGE 71680
#define ATT_SMEM (36864 + 2*AKV_STAGE)
#define SCALE_L2E 0.18033688011112042f   // 0.125 * log2(e)

__global__ __launch_bounds__(256) void attn_mma_kernel(
    const float* __restrict__ ln_w, const float* __restrict__ ln_b)
{
    extern __shared__ char smem[];
    const uint32_t sb = smem_u32(smem);
    const int tid = threadIdx.x, lane = tid & 31, wid = tid >> 5;
    const int br = wid >> 2, wr = wid & 3;
    // heavy tiles (large qt) first: reduces last-wave tail
    const int qt = (int)gridDim.x - 1 - (int)blockIdx.x;
    const int h = blockIdx.y, b = blockIdx.z;
    const int q0 = qt * 64;
    const int bh = b*HH + h;
    const size_t qkbase = (size_t)bh * SDIM * 64;
    const size_t vbase  = (size_t)bh * SDIM * 128;

    {
        const int rq = (tid >> 3), jq = tid & 7;
#pragma unroll
        for (int u = 0; u < 8; u++) {
            const int row = rq + (u & 1)*32;
            const __nv_bfloat16* src = (u < 2) ? g_q1h : (u < 4) ? g_q1l : (u < 6) ? g_q2h : g_q2l;
            cpasync16(sb + (u >> 1)*AQ_TILE + row*AKT_STRIDE + jq*16,
                      src + qkbase + (size_t)(q0 + row)*64 + jq*8);
        }
        const uint32_t kb = sb + 36864;
#pragma unroll
        for (int u = 0; u < 8; u++) {
            const int row = rq + (u & 1)*32;
            const __nv_bfloat16* src = (u < 2) ? g_k1h : (u < 4) ? g_k1l : (u < 6) ? g_k2h : g_k2l;
            cpasync16(kb + (u >> 1)*AQ_TILE + row*AKT_STRIDE + jq*16,
                      src + qkbase + (size_t)row*64 + jq*8);
        }
        const uint32_t vb = kb + 4*AQ_TILE;
        const int rv = (tid >> 4), jv = tid & 15;
#pragma unroll
        for (int u = 0; u < 8; u++) {
            const int row = rv + (u & 3)*16;
            const __nv_bfloat16* src = (u < 4) ? g_vh : g_vl;
            cpasync16(vb + (u >> 2)*AV_TILE + row*AVT_STRIDE + jv*16,
                      src + vbase + (size_t)row*128 + jv*8);
        }
        cp_commit();
    }

    const int lt = lane >> 3, lj = lane & 7;
    const uint32_t qa_off = (uint32_t)(wr*16 + (lt & 1)*8 + lj)*AKT_STRIDE + (uint32_t)(lt >> 1)*16;
    const uint32_t kb_off = (uint32_t)((lt >> 1)*8 + lj)*AKT_STRIDE + (uint32_t)(lt & 1)*16;
    const uint32_t vb_off = (uint32_t)((lt & 1)*8 + lj)*AVT_STRIDE + (uint32_t)(lt >> 1)*16;
    const uint32_t qh_base = sb + br*2*AQ_TILE;
    const uint32_t ql_base = qh_base + AQ_TILE;

    float acc[16][4];
#pragma unroll
    for (int n = 0; n < 16; n++)
#pragma unroll
        for (int c = 0; c < 4; c++) acc[n][c] = 0.f;
    float m0 = -1e30f, m1 = -1e30f, l0 = 0.f, l1 = 0.f;

    const int row_l = wr*16 + (lane >> 2);
    const int nIter = qt + 1;

    for (int kt = 0; kt < nIter; kt++) {
        if (kt + 1 < nIter) {
            const int k0n = (kt + 1) * 64;
            const uint32_t kb = sb + 36864 + ((kt + 1) & 1)*AKV_STAGE;
            const int rq = (tid >> 3), jq = tid & 7;
#pragma unroll
            for (int u = 0; u < 8; u++) {
                const int row = rq + (u & 1)*32;
                const __nv_bfloat16* src = (u < 2) ? g_k1h : (u < 4) ? g_k1l : (u < 6) ? g_k2h : g_k2l;
                cpasync16(kb + (u >> 1)*AQ_TILE + row*AKT_STRIDE + jq*16,
                          src + qkbase + (size_t)(k0n + row)*64 + jq*8);
            }
            const uint32_t vb = kb + 4*AQ_TILE;
            const int rv = (tid >> 4), jv = tid & 15;
#pragma unroll
            for (int u = 0; u < 8; u++) {
                const int row = rv + (u & 3)*16;
                const __nv_bfloat16* src = (u < 4) ? g_vh : g_vl;
                cpasync16(vb + (u >> 2)*AV_TILE + row*AVT_STRIDE + jv*16,
                          src + vbase + (size_t)(k0n + row)*128 + jv*8);
            }
            cp_commit();
            asm volatile("cp.async.wait_group 1;" ::: "memory");
        } else {
            asm volatile("cp.async.wait_group 0;" ::: "memory");
        }
        __syncthreads();

        const uint32_t stg = sb + 36864 + (kt & 1)*AKV_STAGE;
        const uint32_t kh_base = stg + br*2*AQ_TILE;
        const uint32_t kl_base = kh_base + AQ_TILE;
        const uint32_t vh_base = stg + 4*AQ_TILE;
        const uint32_t vl_base = vh_base + AV_TILE;

        float sacc[8][4];
#pragma unroll
        for (int g = 0; g < 8; g++)
#pragma unroll
            for (int c = 0; c < 4; c++) sacc[g][c] = 0.f;
#pragma unroll
        for (int ka = 0; ka < 4; ka++) {
            uint32_t ah[4], al[4];
            ldm4(ah, qh_base + qa_off + ka*32);
            ldm4(al, ql_base + qa_off + ka*32);
#pragma unroll
            for (int g2 = 0; g2 < 4; g2++) {
                uint32_t bh4[4], bl4[4];
                ldm4(bh4, kh_base + g2*(16*AKT_STRIDE) + kb_off + ka*32);
                ldm4(bl4, kl_base + g2*(16*AKT_STRIDE) + kb_off + ka*32);
#pragma unroll
                for (int hf = 0; hf < 2; hf++) {
                    float* C = sacc[g2*2 + hf];
                    mma16816(C, ah, bh4[hf*2], bh4[hf*2+1]);
                    mma16816(C, ah, bl4[hf*2], bl4[hf*2+1]);
                    mma16816(C, al, bh4[hf*2], bh4[hf*2+1]);
                }
            }
        }

        const bool diag = (kt == qt);
        float t0 = -1e30f, t1 = -1e30f;
#pragma unroll
        for (int g = 0; g < 8; g++) {
            const int cb = g*8 + (lane & 3)*2;
#pragma unroll
            for (int c = 0; c < 4; c++) {
                float s = sacc[g][c] * SCALE_L2E;
                if (diag) {
                    const int rr = row_l + (c >= 2 ? 8 : 0);
                    const int cc = cb + (c & 1);
                    if (cc > rr) s = -1e30f;
                }
                sacc[g][c] = s;
            }
            t0 = fmaxf(t0, fmaxf(sacc[g][0], sacc[g][1]));
            t1 = fmaxf(t1, fmaxf(sacc[g][2], sacc[g][3]));
        }
        t0 = fmaxf(t0, __shfl_xor_sync(0xffffffffu, t0, 1));
        t0 = fmaxf(t0, __shfl_xor_sync(0xffffffffu, t0, 2));
        t1 = fmaxf(t1, __shfl_xor_sync(0xffffffffu, t1, 1));
        t1 = fmaxf(t1, __shfl_xor_sync(0xffffffffu, t1, 2));
        const float mn0 = fmaxf(m0, t0), mn1 = fmaxf(m1, t1);
        const float alpha0 = exp2f(m0 - mn0), alpha1 = exp2f(m1 - mn1);
        m0 = mn0; m1 = mn1;

        float rs0 = 0.f, rs1 = 0.f;
#pragma unroll
        for (int g = 0; g < 8; g++) {
            float p0 = exp2f(sacc[g][0] - mn0);
            float p1 = exp2f(sacc[g][1] - mn0);
            float p2 = exp2f(sacc[g][2] - mn1);
            float p3 = exp2f(sacc[g][3] - mn1);
            sacc[g][0] = p0; sacc[g][1] = p1; sacc[g][2] = p2; sacc[g][3] = p3;
            rs0 += p0 + p1; rs1 += p2 + p3;
        }
        rs0 += __shfl_xor_sync(0xffffffffu, rs0, 1);
        rs0 += __shfl_xor_sync(0xffffffffu, rs0, 2);
        rs1 += __shfl_xor_sync(0xffffffffu, rs1, 1);
        rs1 += __shfl_xor_sync(0xffffffffu, rs1, 2);
        l0 = l0*alpha0 + rs0;
        l1 = l1*alpha1 + rs1;

#pragma unroll
        for (int n = 0; n < 16; n++) {
            acc[n][0] *= alpha0; acc[n][1] *= alpha0;
            acc[n][2] *= alpha1; acc[n][3] *= alpha1;
        }

#pragma unroll
        for (int ka = 0; ka < 4; ka++) {
            uint32_t ph[4], pl[4];
#pragma unroll
            for (int half = 0; half < 2; half++) {
                const int g = 2*ka + half;
                float v0 = sacc[g][0], v1 = sacc[g][1], v2 = sacc[g][2], v3 = sacc[g][3];
                __nv_bfloat16 b0 = __float2bfloat16(v0), b1v = __float2bfloat16(v1);
                __nv_bfloat16 b2 = __float2bfloat16(v2), b3 = __float2bfloat16(v3);
                __nv_bfloat162 t01 = __halves2bfloat162(b0, b1v);
                __nv_bfloat162 t23 = __halves2bfloat162(b2, b3);
                ph[half*2 + 0] = *(uint32_t*)&t01;
                ph[half*2 + 1] = *(uint32_t*)&t23;
                pl[half*2 + 0] = packbf(v0 - __bfloat162float(b0), v1 - __bfloat162float(b1v));
                pl[half*2 + 1] = packbf(v2 - __bfloat162float(b2), v3 - __bfloat162float(b3));
            }
#pragma unroll
            for (int np = 0; np < 8; np++) {
                uint32_t vh4[4], vl4[4];
                ldm4t(vh4, vh_base + ka*(16*AVT_STRIDE) + vb_off + np*32);
                ldm4t(vl4, vl_base + ka*(16*AVT_STRIDE) + vb_off + np*32);
#pragma unroll
                for (int hf = 0; hf < 2; hf++) {
                    float* C = acc[np*2 + hf];
                    mma16816(C, ph, vh4[hf*2], vh4[hf*2+1]);
                    mma16816(C, ph, vl4[hf*2], vl4[hf*2+1]);
                    mma16816(C, pl, vh4[hf*2], vh4[hf*2+1]);
                }
            }
        }
        __syncthreads();
    }

    const float inv0 = 1.f / l0, inv1 = 1.f / l1;
#pragma unroll
    for (int n = 0; n < 16; n++) {
        acc[n][0] *= inv0; acc[n][1] *= inv0;
        acc[n][2] *= inv1; acc[n][3] *= inv1;
    }

    float* sO = (float*)smem;
    const int rl = row_l, rh = row_l + 8;
    __syncthreads();
    if (br == 1) {
#pragma unroll
        for (int n = 0; n < 16; n++) {
            const int c = n*8 + (lane & 3)*2;
            float2 a; a.x = acc[n][0]; a.y = acc[n][1];
            float2 bvv; bvv.x = acc[n][2]; bvv.y = acc[n][3];
            *(float2*)&sO[rl*128 + c] = a;
            *(float2*)&sO[rh*128 + c] = bvv;
        }
    }
    __syncthreads();
    if (br == 0) {
        const float lam = g_lambda;
        const float osc = 1.f - LAMBDA_INIT_F;
        float ssq0 = 0.f, ssq1 = 0.f;
#pragma unroll
        for (int n = 0; n < 16; n++) {
            const int c = n*8 + (lane & 3)*2;
            float2 o2l = *(float2*)&sO[rl*128 + c];
            float2 o2h = *(float2*)&sO[rh*128 + c];
            acc[n][0] -= lam*o2l.x; acc[n][1] -= lam*o2l.y;
            acc[n][2] -= lam*o2h.x; acc[n][3] -= lam*o2h.y;
            ssq0 += acc[n][0]*acc[n][0] + acc[n][1]*acc[n][1];
            ssq1 += acc[n][2]*acc[n][2] + acc[n][3]*acc[n][3];
        }
        ssq0 += __shfl_xor_sync(0xffffffffu, ssq0, 1);
        ssq0 += __shfl_xor_sync(0xffffffffu, ssq0, 2);
        ssq1 += __shfl_xor_sync(0xffffffffu, ssq1, 1);
        ssq1 += __shfl_xor_sync(0xffffffffu, ssq1, 2);
        const float rms0 = rsqrtf(ssq0 * (1.f/128.f) + 1e-8f);
        const float rms1 = rsqrtf(ssq1 * (1.f/128.f) + 1e-8f);
        const size_t ob_l = ((size_t)(b*SDIM + q0 + rl))*DDIM + h*128;
        const size_t ob_h = ((size_t)(b*SDIM + q0 + rh))*DDIM + h*128;
#pragma unroll
        for (int n = 0; n < 16; n++) {
            const int c = n*8 + (lane & 3)*2;
            float w0 = __ldg(&ln_w[c]), w1 = __ldg(&ln_w[c+1]);
            float bb0 = __ldg(&ln_b[c]), bb1 = __ldg(&ln_b[c+1]);
            float v0 = (acc[n][0]*rms0*w0 + bb0) * osc;
            float v1 = (acc[n][1]*rms0*w1 + bb1) * osc;
            float v2 = (acc[n][2]*rms1*w0 + bb0) * osc;
            float v3 = (acc[n][3]*rms1*w1 + bb1) * osc;
            __nv_bfloat16 h0 = __float2bfloat16(v0), h1v = __float2bfloat16(v1);
            __nv_bfloat16 h2 = __float2bfloat16(v2), h3 = __float2bfloat16(v3);
            *(__nv_bfloat162*)&g_attnh[ob_l + c] = __halves2bfloat162(h0, h1v);
            *(__nv_bfloat162*)&g_attnl[ob_l + c] = __floats2bfloat162_rn(
                v0 - __bfloat162float(h0), v1 - __bfloat162float(h1v));
            *(__nv_bfloat162*)&g_attnh[ob_h + c] = __halves2bfloat162(h2, h3);
            *(__nv_bfloat162*)&g_attnl[ob_h + c] = __floats2bfloat162_rn(
                v2 - __bfloat162float(h2), v3 - __bfloat162float(h3));
        }
    }
}

// ================= layernorm over 1024 (+ optional fp16/64 out) =================
__global__ __launch_bounds__(256) void layernorm_kernel(
    const float* __restrict__ in, const float* __restrict__ w, const float* __restrict__ bb,
    float* __restrict__ out, __half* __restrict__ oh16)
{
    __shared__ float red1[8], red2[8];
    const int row = blockIdx.x;
    const float* x = in + (size_t)row * DDIM;
    float v[4];
    float s = 0.f, s2 = 0.f;
#pragma unroll
    for (int it = 0; it < 4; it++) {
        float t = x[threadIdx.x + it*256];
        v[it] = t; s += t; s2 += t*t;
    }
#pragma unroll
    for (int o = 16; o; o >>= 1) {
        s  += __shfl_xor_sync(0xffffffffu, s,  o);
        s2 += __shfl_xor_sync(0xffffffffu, s2, o);
    }
    const int lane = threadIdx.x & 31, wp = threadIdx.x >> 5;
    if (lane == 0) { red1[wp] = s; red2[wp] = s2; }
    __syncthreads();
    if (wp == 0) {
        s  = (lane < 8) ? red1[lane] : 0.f;
        s2 = (lane < 8) ? red2[lane] : 0.f;
#pragma unroll
        for (int o = 4; o; o >>= 1) {
            s  += __shfl_xor_sync(0xffffffffu, s,  o);
            s2 += __shfl_xor_sync(0xffffffffu, s2, o);
        }
        if (lane == 0) { red1[0] = s * (1.f/1024.f); red2[0] = s2 * (1.f/1024.f); }
    }
    __syncthreads();
    const float mean = red1[0];
    const float var = red2[0] - mean*mean;
    const float rstd = rsqrtf(var + 1e-5f);
#pragma unroll
    for (int it = 0; it < 4; it++) {
        int c = threadIdx.x + it*256;
        size_t idx = (size_t)row*DDIM + c;
        float y = (v[it] - mean)*rstd*w[c] + bb[c];
        out[idx] = y;
        if (oh16) oh16[idx] = __float2half(y * 0.015625f);
    }
}

// ================= launch =================
extern "C" void kernel_launch(void* const* d_in, const int* in_sizes, int n_in,
                              void* d_out, int out_size)
{
    (void)in_sizes; (void)n_in; (void)out_size;
    const float* x      = (const float*)d_in[0];
    const float* sigmas = (const float*)d_in[1];
    const float* w_qkv  = (const float*)d_in[2];
    const float* w_out  = (const float*)d_in[3];
    const float* lq1    = (const float*)d_in[4];
    const float* lk1    = (const float*)d_in[5];
    const float* lq2    = (const float*)d_in[6];
    const float* lk2    = (const float*)d_in[7];
    const float* ln_w   = (const float*)d_in[8];
    const float* ln_b   = (const float*)d_in[9];
    const float* lnq_w  = (const float*)d_in[10];
    const float* lnq_b  = (const float*)d_in[11];
    const float* ln1_w  = (const float*)d_in[12];
    const float* ln1_b  = (const float*)d_in[13];
    const float* ln2_w  = (const float*)d_in[14];
    const float* ln2_b  = (const float*)d_in[15];
    const float* w1     = (const float*)d_in[16];
    const float* b1     = (const float*)d_in[17];
    const float* w2     = (const float*)d_in[18];
    const float* b2     = (const float*)d_in[19];
    float* out = (float*)d_out;

    void *p_qkv, *p_tmp1, *p_h, *p_f2;
    void *p_xh, *p_xl, *p_wqkvTh, *p_wqkvTl, *p_woutTh, *p_woutTl;
    void *p_attnh, *p_attnl;
    void *p_h16, *p_ff116, *p_w1h, *p_w1l, *p_w2h, *p_w2l;
    cudaGetSymbolAddress(&p_qkv,  g_qkv);
    cudaGetSymbolAddress(&p_tmp1, g_tmp1);
    cudaGetSymbolAddress(&p_h,    g_h);
    cudaGetSymbolAddress(&p_f2,   g_f2);
    cudaGetSymbolAddress(&p_xh, g_xh);       cudaGetSymbolAddress(&p_xl, g_xl);
    cudaGetSymbolAddress(&p_wqkvTh, g_wqkvTh); cudaGetSymbolAddress(&p_wqkvTl, g_wqkvTl);
    cudaGetSymbolAddress(&p_woutTh, g_woutTh); cudaGetSymbolAddress(&p_woutTl, g_woutTl);
    cudaGetSymbolAddress(&p_attnh, g_attnh); cudaGetSymbolAddress(&p_attnl, g_attnl);
    cudaGetSymbolAddress(&p_h16, g_h16);     cudaGetSymbolAddress(&p_ff116, g_ff116);
    cudaGetSymbolAddress(&p_w1h, g_w1T16h);  cudaGetSymbolAddress(&p_w1l, g_w1T16l);
    cudaGetSymbolAddress(&p_w2h, g_w2T16h);  cudaGetSymbolAddress(&p_w2l, g_w2T16l);

    cudaFuncSetAttribute(gemm_mma_kernel, cudaFuncAttributeMaxDynamicSharedMemorySize, GEMM_SMEM);
    cudaFuncSetAttribute(gemm_f16_kernel, cudaFuncAttributeMaxDynamicSharedMemorySize, GEMMF_SMEM);
    cudaFuncSetAttribute(attn_mma_kernel, cudaFuncAttributeMaxDynamicSharedMemorySize, ATT_SMEM);

    lambda_kernel<<<1, 32>>>(lq1, lk1, lq2, lk2);

    split_kernel<<<(MROWS*DDIM/4 + 255)/256, 256>>>(x, (__nv_bfloat16*)p_xh, (__nv_bfloat16*)p_xl, MROWS*DDIM/4);
    transpose_split_kernel<<<dim3(3072/32, 1024/32), dim3(32,8)>>>(w_qkv, (__nv_bfloat16*)p_wqkvTh, (__nv_bfloat16*)p_wqkvTl, 1024, 3072);
    transpose_split_kernel<<<dim3(1024/32, 1024/32), dim3(32,8)>>>(w_out, (__nv_bfloat16*)p_woutTh, (__nv_bfloat16*)p_woutTl, 1024, 1024);
    transpose_split_f16_kernel<<<dim3(4096/32, 1024/32), dim3(32,8)>>>(w1, (__half*)p_w1h, (__half*)p_w1l, 1024, 4096);
    transpose_split_f16_kernel<<<dim3(1024/32, 4096/32), dim3(32,8)>>>(w2, (__half*)p_w2h, (__half*)p_w2l, 4096, 1024);

    // qkv = x @ w_qkv (bf16x3)
    gemm_mma_kernel<<<dim3(3072/128, 4096/128), 256, GEMM_SMEM>>>(
        (const __nv_bfloat16*)p_xh, (const __nv_bfloat16*)p_xl,
        (const __nv_bfloat16*)p_wqkvTh, (const __nv_bfloat16*)p_wqkvTl,
        (float*)p_qkv, MROWS, 3072, 1024, nullptr, nullptr, 0);

    rope_split_kernel<<<MROWS, 256>>>(sigmas, lnq_w, lnq_b);

    attn_mma_kernel<<<dim3(SDIM/64, HH, BDIM), 256, ATT_SMEM>>>(ln_w, ln_b);

    // tmp1 = attn @ w_out + x (bf16x3)
    gemm_mma_kernel<<<dim3(1024/128, 4096/128), 256, GEMM_SMEM>>>(
        (const __nv_bfloat16*)p_attnh, (const __nv_bfloat16*)p_attnl,
        (const __nv_bfloat16*)p_woutTh, (const __nv_bfloat16*)p_woutTl,
        (float*)p_tmp1, MROWS, 1024, 1024, nullptr, x, 0);

    layernorm_kernel<<<MROWS, 256>>>((const float*)p_tmp1, ln1_w, ln1_b,
        (float*)p_h, (__half*)p_h16);

    // ff1 = silu(h @ w1 + b1) (fp16 2-term), out fp16/64
    gemm_f16_kernel<<<dim3(4096/128, 4096/128), 256, GEMMF_SMEM>>>(
        (const __half*)p_h16, (const __half*)p_w1h, (const __half*)p_w1l,
        nullptr, (__half*)p_ff116, MROWS, 4096, 1024, b1, nullptr, 1);

    // f2 = ff1 @ w2 + b2 + h (fp16 2-term)
    gemm_f16_kernel<<<dim3(1024/128, 4096/128), 256, GEMMF_SMEM>>>(
        (const __half*)p_ff116, (const __half*)p_w2h, (const __half*)p_w2l,
        (float*)p_f2, nullptr, MROWS, 1024, 4096, b2, (const float*)p_h, 0);

    layernorm_kernel<<<MROWS, 256>>>((const float*)p_f2, ln2_w, ln2_b, out, nullptr);
}

// round 7
// speedup vs baseline: 3.0483x; 1.1624x over previous
#include <cuda_runtime.h>
#include <cuda_bf16.h>
#include <cuda_fp16.h>
#include <math.h>
#include <stdint.h>

// Problem constants
#define BDIM 2
#define SDIM 2048
#define DDIM 1024
#define HH   8
#define MROWS (BDIM*SDIM)          // 4096
static __device__ __constant__ float LAMBDA_INIT_F = 0.470713018343584f; // 0.8 - 0.6*exp(-0.6)

// ================= scratch (device globals) =================
__device__ float g_lambda;
__device__ float g_qkv [MROWS * 3 * DDIM];
__device__ float g_tmp1[MROWS * DDIM];
__device__ float g_h   [MROWS * DDIM];
__device__ float g_f2  [MROWS * DDIM];

// attention operands: bf16 hi/lo, [b,h,s,64] / [b,h,s,128]
#define QKELEM (BDIM*HH*SDIM*64)
__device__ __nv_bfloat16 g_q1h[QKELEM], g_q1l[QKELEM];
__device__ __nv_bfloat16 g_k1h[QKELEM], g_k1l[QKELEM];
__device__ __nv_bfloat16 g_q2h[QKELEM], g_q2l[QKELEM];
__device__ __nv_bfloat16 g_k2h[QKELEM], g_k2l[QKELEM];
__device__ __nv_bfloat16 g_vh[BDIM*HH*SDIM*128], g_vl[BDIM*HH*SDIM*128];

// fp16 staging: activations plain fp16, weights x64 hi/lo, epilogue applies 1/64
__device__ __half g_x16  [MROWS*DDIM];
__device__ __half g_attn16[MROWS*DDIM];
__device__ __half g_h16  [MROWS*DDIM];
__device__ __half g_ff116[MROWS*4*DDIM];
__device__ __half g_wqkvT16h[3*DDIM*DDIM], g_wqkvT16l[3*DDIM*DDIM];  // [3072,1024]
__device__ __half g_woutT16h[DDIM*DDIM],   g_woutT16l[DDIM*DDIM];    // [1024,1024]
__device__ __half g_w1T16h[4*DDIM*DDIM],   g_w1T16l[4*DDIM*DDIM];    // [4096,1024]
__device__ __half g_w2T16h[DDIM*4*DDIM],   g_w2T16l[DDIM*4*DDIM];    // [1024,4096]

// ================= helpers =================
__device__ __forceinline__ uint32_t smem_u32(const void* p) {
    uint32_t a;
    asm("{ .reg .u64 t; cvta.to.shared.u64 t, %1; cvt.u32.u64 %0, t; }" : "=r"(a) : "l"(p));
    return a;
}
__device__ __forceinline__ void cpasync16(uint32_t dst, const void* src) {
    asm volatile("cp.async.cg.shared.global [%0], [%1], 16;" :: "r"(dst), "l"(src));
}
__device__ __forceinline__ void cp_commit() { asm volatile("cp.async.commit_group;" ::: "memory"); }
__device__ __forceinline__ void ldm4(uint32_t* r, uint32_t addr) {
    asm volatile("ldmatrix.sync.aligned.m8n8.x4.shared.b16 {%0,%1,%2,%3}, [%4];"
        : "=r"(r[0]), "=r"(r[1]), "=r"(r[2]), "=r"(r[3]) : "r"(addr));
}
__device__ __forceinline__ void ldm4t(uint32_t* r, uint32_t addr) {
    asm volatile("ldmatrix.sync.aligned.m8n8.x4.trans.shared.b16 {%0,%1,%2,%3}, [%4];"
        : "=r"(r[0]), "=r"(r[1]), "=r"(r[2]), "=r"(r[3]) : "r"(addr));
}
__device__ __forceinline__ void mma16816(float* c, const uint32_t* a, uint32_t b0, uint32_t b1) {
    asm volatile("mma.sync.aligned.m16n8k16.row.col.f32.bf16.bf16.f32 "
        "{%0,%1,%2,%3}, {%4,%5,%6,%7}, {%8,%9}, {%0,%1,%2,%3};"
        : "+f"(c[0]), "+f"(c[1]), "+f"(c[2]), "+f"(c[3])
        : "r"(a[0]), "r"(a[1]), "r"(a[2]), "r"(a[3]), "r"(b0), "r"(b1));
}
__device__ __forceinline__ void mma16816h(float* c, const uint32_t* a, uint32_t b0, uint32_t b1) {
    asm volatile("mma.sync.aligned.m16n8k16.row.col.f32.f16.f16.f32 "
        "{%0,%1,%2,%3}, {%4,%5,%6,%7}, {%8,%9}, {%0,%1,%2,%3};"
        : "+f"(c[0]), "+f"(c[1]), "+f"(c[2]), "+f"(c[3])
        : "r"(a[0]), "r"(a[1]), "r"(a[2]), "r"(a[3]), "r"(b0), "r"(b1));
}
__device__ __forceinline__ uint32_t packbf(float a, float b) {
    __nv_bfloat162 t = __floats2bfloat162_rn(a, b);
    return *(uint32_t*)&t;
}

// ================= lambda =================
__global__ void lambda_kernel(const float* __restrict__ lq1, const float* __restrict__ lk1,
                              const float* __restrict__ lq2, const float* __restrict__ lk2)
{
    int lane = threadIdx.x;
    float s1 = lq1[lane]*lk1[lane] + lq1[lane+32]*lk1[lane+32];
    float s2 = lq2[lane]*lk2[lane] + lq2[lane+32]*lk2[lane+32];
#pragma unroll
    for (int o = 16; o; o >>= 1) {
        s1 += __shfl_xor_sync(0xffffffffu, s1, o);
        s2 += __shfl_xor_sync(0xffffffffu, s2, o);
    }
    if (lane == 0) g_lambda = expf(s1) - expf(s2) + LAMBDA_INIT_F;
}

// ================= fp32 -> plain fp16 =================
__global__ __launch_bounds__(256) void split_f16_kernel(const float* __restrict__ in,
    __half* __restrict__ o, int n4)
{
    int i = blockIdx.x * 256 + threadIdx.x;
    if (i >= n4) return;
    float4 v = ((const float4*)in)[i];
    ((__half2*)o)[2*i]   = __floats2half2_rn(v.x, v.y);
    ((__half2*)o)[2*i+1] = __floats2half2_rn(v.z, v.w);
}

// ================= transpose + split fp16 x64: in[K,N] fp32 -> out[N,K] fp16 hi/lo (x64) ====
__global__ __launch_bounds__(256) void transpose_split_f16_kernel(const float* __restrict__ in,
    __half* __restrict__ oh, __half* __restrict__ ol, int K, int N)
{
    __shared__ float t[32][33];
    const int k0 = blockIdx.y*32, n0 = blockIdx.x*32;
    const int tx = threadIdx.x, ty = threadIdx.y;
#pragma unroll
    for (int i = 0; i < 4; i++)
        t[ty + i*8][tx] = in[(size_t)(k0 + ty + i*8)*N + n0 + tx];
    __syncthreads();
#pragma unroll
    for (int i = 0; i < 4; i++) {
        int n = n0 + ty + i*8, k = k0 + tx;
        float v = t[tx][ty + i*8] * 64.f;
        __half hv = __float2half(v);
        oh[(size_t)n*K + k] = hv;
        ol[(size_t)n*K + k] = __float2half(v - __half2float(hv));
    }
}

// ================= mma.sync fp16 2-term GEMM =================
// C[M,N] = (A[M,K] @ (Bh+Bl)[N,K]^T) * oscale (+bias)(silu?)(+resid)
// A plain fp16; B fp16 hi/lo scaled x64; oscale = 1/64 undoes the weight scale.
#define F_TILE_B  10240
#define F_STAGE_B 30720
#define GEMMF_SMEM (2*F_STAGE_B)

__global__ __launch_bounds__(256) void gemm_f16_kernel(
    const __half* __restrict__ Ah,
    const __half* __restrict__ Bh, const __half* __restrict__ Bl,
    float* __restrict__ Cf, __half* __restrict__ Ch16,
    int M, int N, int K, float oscale,
    const float* __restrict__ bias, const float* __restrict__ resid, int act)
{
    extern __shared__ char smem[];
    const uint32_t sb = smem_u32(smem);
    const int tid = threadIdx.x;
    const int lane = tid & 31;
    const int wid = tid >> 5;
    const int bm = blockIdx.y * 128;
    const int bn = blockIdx.x * 128;
    const int wm = wid >> 1;
    const int wn = wid & 1;

    const int lrow  = tid >> 1;
    const int lhalf = (tid & 1) * 32;
    const size_t rowB = (size_t)K * 2;
    const char* gA  = (const char*)Ah + (size_t)(bm + lrow) * rowB + lhalf;
    const char* gBh = (const char*)Bh + (size_t)(bn + lrow) * rowB + lhalf;
    const char* gBl = (const char*)Bl + (size_t)(bn + lrow) * rowB + lhalf;
    const uint32_t sdst = sb + (uint32_t)lrow * 80u + (uint32_t)lhalf;

    const int nChunks = K >> 5;

    {
        uint32_t d = sdst;
        cpasync16(d,             gA);       cpasync16(d + 16,             gA + 16);
        cpasync16(d + F_TILE_B,  gBh);      cpasync16(d + F_TILE_B + 16,  gBh + 16);
        cpasync16(d + 2*F_TILE_B, gBl);     cpasync16(d + 2*F_TILE_B + 16, gBl + 16);
        cp_commit();
    }

    float acc[2][8][4];
#pragma unroll
    for (int i = 0; i < 2; i++)
#pragma unroll
        for (int j = 0; j < 8; j++)
#pragma unroll
            for (int k = 0; k < 4; k++) acc[i][j][k] = 0.f;

    const int lt = lane >> 3, lj = lane & 7;
    const uint32_t a_row = (uint32_t)(wm*32 + (lt & 1)*8 + lj) * 80u;
    const uint32_t a_col = (uint32_t)((lt >> 1) * 8) * 2u;
    const uint32_t b_row = (uint32_t)(wn*64 + (lt >> 1)*8 + lj) * 80u;
    const uint32_t b_col = (uint32_t)((lt & 1) * 8) * 2u;

    for (int c = 0; c < nChunks; c++) {
        if (c + 1 < nChunks) {
            const uint32_t d = sdst + (uint32_t)((c + 1) & 1) * F_STAGE_B;
            const size_t go = (size_t)(c + 1) * 64;
            cpasync16(d,              gA + go);   cpasync16(d + 16,              gA + go + 16);
            cpasync16(d + F_TILE_B,   gBh + go);  cpasync16(d + F_TILE_B + 16,   gBh + go + 16);
            cpasync16(d + 2*F_TILE_B, gBl + go);  cpasync16(d + 2*F_TILE_B + 16, gBl + go + 16);
            cp_commit();
            asm volatile("cp.async.wait_group 1;" ::: "memory");
        } else {
            asm volatile("cp.async.wait_group 0;" ::: "memory");
        }
        __syncthreads();

        const uint32_t base = sb + (uint32_t)(c & 1) * F_STAGE_B;
#pragma unroll
        for (int ks = 0; ks < 2; ks++) {
            const uint32_t kofs = (uint32_t)ks * 32u;
            uint32_t af[2][4];
#pragma unroll
            for (int ma = 0; ma < 2; ma++)
                ldm4(af[ma], base + a_row + (uint32_t)ma*16u*80u + a_col + kofs);
            uint32_t bfh[4][4], bfl[4][4];
#pragma unroll
            for (int g = 0; g < 4; g++) {
                ldm4(bfh[g], base + F_TILE_B   + b_row + (uint32_t)g*16u*80u + b_col + kofs);
                ldm4(bfl[g], base + 2*F_TILE_B + b_row + (uint32_t)g*16u*80u + b_col + kofs);
            }
#pragma unroll
            for (int ma = 0; ma < 2; ma++)
#pragma unroll
                for (int g = 0; g < 4; g++)
#pragma unroll
                    for (int hf = 0; hf < 2; hf++) {
                        float* C = acc[ma][g*2 + hf];
                        mma16816h(C, af[ma], bfh[g][hf*2], bfh[g][hf*2+1]);
                        mma16816h(C, af[ma], bfl[g][hf*2], bfl[g][hf*2+1]);
                    }
        }
        __syncthreads();
    }

#pragma unroll
    for (int ma = 0; ma < 2; ma++)
#pragma unroll
        for (int na = 0; na < 8; na++) {
            const int r0 = bm + wm*32 + ma*16 + (lane >> 2);
            const int c0 = bn + wn*64 + na*8 + 2*(lane & 3);
#pragma unroll
            for (int half = 0; half < 2; half++) {
                const int r = r0 + half*8;
                float v0 = acc[ma][na][half*2 + 0] * oscale;
                float v1 = acc[ma][na][half*2 + 1] * oscale;
                if (bias) { v0 += bias[c0]; v1 += bias[c0 + 1]; }
                if (act) {
                    v0 = v0 / (1.f + __expf(-v0));
                    v1 = v1 / (1.f + __expf(-v1));
                }
                const size_t o = (size_t)r * N + c0;
                if (resid) { v0 += resid[o]; v1 += resid[o + 1]; }
                if (Cf) { float2 f2o; f2o.x = v0; f2o.y = v1; *(float2*)&Cf[o] = f2o; }
                if (Ch16) *(__half2*)&Ch16[o] = __floats2half2_rn(v0, v1);
            }
        }
}

// ================= RoPE + head split + q2/k2 rmsnorm + V repack (bf16 hi/lo out) ==========
__global__ __launch_bounds__(256) void rope_split_kernel(
    const float* __restrict__ sigmas, const float* __restrict__ lnq_w, const float* __restrict__ lnq_b)
{
    const int row = blockIdx.x;
    const int b = row / SDIM, s = row % SDIM;
    const float* base = g_qkv + (size_t)row * 3072;
    const int lane = threadIdx.x & 31;
    const int warp = threadIdx.x >> 5;

    for (int idx = threadIdx.x; idx < 1024; idx += 256) {
        int h = idx >> 7, e = idx & 127;
        float val = base[2048 + idx];
        size_t o = (((size_t)b*HH + h)*SDIM + s)*128 + e;
        __nv_bfloat16 hv = __float2bfloat16(val);
        g_vh[o] = hv;
        g_vl[o] = __float2bfloat16(val - __bfloat162float(hv));
    }

    int p = lane >> 1;
    float inv = (float)exp(-(double)p * 0.57564627324851148);
    float fr = (float)s * inv;
    float c0 = cosf(fr), s0 = sinf(fr);

    for (int t = warp; t < 32; t += 8) {
        const int which = t >> 4;
        const int h2 = t & 15;
        const float* src = base + which*1024 + h2*64;
        float x0 = src[lane];
        float x1 = src[lane + 32];
        float partner = src[lane ^ 1];
        float r0 = (lane & 1) ? fmaf(x0, c0,  partner * s0)
                              : fmaf(x0, c0, -partner * s0);
        const int h = h2 >> 1, comp = h2 & 1;
        size_t off = (((size_t)b*HH + h)*SDIM + s)*64;
        if (comp == 0) {
            __nv_bfloat16* dh = which ? g_k1h : g_q1h;
            __nv_bfloat16* dl = which ? g_k1l : g_q1l;
            __nv_bfloat16 h0 = __float2bfloat16(r0);
            __nv_bfloat16 h1 = __float2bfloat16(x1);
            dh[off + lane]      = h0;
            dh[off + lane + 32] = h1;
            dl[off + lane]      = __float2bfloat16(r0 - __bfloat162float(h0));
            dl[off + lane + 32] = __float2bfloat16(x1 - __bfloat162float(h1));
        } else {
            float a0 = r0 + sigmas[b*64 + lane];
            float a1 = x1 + sigmas[b*64 + lane + 32];
            float ss = a0*a0 + a1*a1;
#pragma unroll
            for (int o = 16; o; o >>= 1) ss += __shfl_xor_sync(0xffffffffu, ss, o);
            float rms = rsqrtf(ss * (1.f/64.f) + 1e-8f);
            float v0 = fmaf(a0*rms, lnq_w[lane],      lnq_b[lane]);
            float v1 = fmaf(a1*rms, lnq_w[lane+32],   lnq_b[lane+32]);
            __nv_bfloat16* dh = which ? g_k2h : g_q2h;
            __nv_bfloat16* dl = which ? g_k2l : g_q2l;
            __nv_bfloat16 h0 = __float2bfloat16(v0);
            __nv_bfloat16 h1 = __float2bfloat16(v1);
            dh[off + lane]      = h0;
            dh[off + lane + 32] = h1;
            dl[off + lane]      = __float2bfloat16(v0 - __bfloat162float(h0));
            dl[off + lane + 32] = __float2bfloat16(v1 - __bfloat162float(h1));
        }
    }
}

// ================= tensor-core dual causal attention + diff + rmsnorm(128) =================
#define AKT_STRIDE 144
#define AVT_STRIDE 272
#define AQ_TILE 9216
#define AV_TILE 17408
#define AKV_STAGE 71680
#define ATT_SMEM (36864 + 2*AKV_STAGE)
#define SCALE_L2E 0.18033688011112042f   // 0.125 * log2(e)

__global__ __launch_bounds__(256) void attn_mma_kernel(
    const float* __restrict__ ln_w, const float* __restrict__ ln_b)
{
    extern __shared__ char smem[];
    const uint32_t sb = smem_u32(smem);
    const int tid = threadIdx.x, lane = tid & 31, wid = tid >> 5;
    const int br = wid >> 2, wr = wid & 3;
    // heavy tiles (large qt) first: reduces last-wave tail
    const int qt = (int)gridDim.x - 1 - (int)blockIdx.x;
    const int h = blockIdx.y, b = blockIdx.z;
    const int q0 = qt * 64;
    const int bh = b*HH + h;
    const size_t qkbase = (size_t)bh * SDIM * 64;
    const size_t vbase  = (size_t)bh * SDIM * 128;

    {
        const int rq = (tid >> 3), jq = tid & 7;
#pragma unroll
        for (int u = 0; u < 8; u++) {
            const int row = rq + (u & 1)*32;
            const __nv_bfloat16* src = (u < 2) ? g_q1h : (u < 4) ? g_q1l : (u < 6) ? g_q2h : g_q2l;
            cpasync16(sb + (u >> 1)*AQ_TILE + row*AKT_STRIDE + jq*16,
                      src + qkbase + (size_t)(q0 + row)*64 + jq*8);
        }
        const uint32_t kb = sb + 36864;
#pragma unroll
        for (int u = 0; u < 8; u++) {
            const int row = rq + (u & 1)*32;
            const __nv_bfloat16* src = (u < 2) ? g_k1h : (u < 4) ? g_k1l : (u < 6) ? g_k2h : g_k2l;
            cpasync16(kb + (u >> 1)*AQ_TILE + row*AKT_STRIDE + jq*16,
                      src + qkbase + (size_t)row*64 + jq*8);
        }
        const uint32_t vb = kb + 4*AQ_TILE;
        const int rv = (tid >> 4), jv = tid & 15;
#pragma unroll
        for (int u = 0; u < 8; u++) {
            const int row = rv + (u & 3)*16;
            const __nv_bfloat16* src = (u < 4) ? g_vh : g_vl;
            cpasync16(vb + (u >> 2)*AV_TILE + row*AVT_STRIDE + jv*16,
                      src + vbase + (size_t)row*128 + jv*8);
        }
        cp_commit();
    }

    const int lt = lane >> 3, lj = lane & 7;
    const uint32_t qa_off = (uint32_t)(wr*16 + (lt & 1)*8 + lj)*AKT_STRIDE + (uint32_t)(lt >> 1)*16;
    const uint32_t kb_off = (uint32_t)((lt >> 1)*8 + lj)*AKT_STRIDE + (uint32_t)(lt & 1)*16;
    const uint32_t vb_off = (uint32_t)((lt & 1)*8 + lj)*AVT_STRIDE + (uint32_t)(lt >> 1)*16;
    const uint32_t qh_base = sb + br*2*AQ_TILE;
    const uint32_t ql_base = qh_base + AQ_TILE;

    float acc[16][4];
#pragma unroll
    for (int n = 0; n < 16; n++)
#pragma unroll
        for (int c = 0; c < 4; c++) acc[n][c] = 0.f;
    float m0 = -1e30f, m1 = -1e30f, l0 = 0.f, l1 = 0.f;

    const int row_l = wr*16 + (lane >> 2);
    const int nIter = qt + 1;

    for (int kt = 0; kt < nIter; kt++) {
        if (kt + 1 < nIter) {
            const int k0n = (kt + 1) * 64;
            const uint32_t kb = sb + 36864 + ((kt + 1) & 1)*AKV_STAGE;
            const int rq = (tid >> 3), jq = tid & 7;
#pragma unroll
            for (int u = 0; u < 8; u++) {
                const int row = rq + (u & 1)*32;
                const __nv_bfloat16* src = (u < 2) ? g_k1h : (u < 4) ? g_k1l : (u < 6) ? g_k2h : g_k2l;
                cpasync16(kb + (u >> 1)*AQ_TILE + row*AKT_STRIDE + jq*16,
                          src + qkbase + (size_t)(k0n + row)*64 + jq*8);
            }
            const uint32_t vb = kb + 4*AQ_TILE;
            const int rv = (tid >> 4), jv = tid & 15;
#pragma unroll
            for (int u = 0; u < 8; u++) {
                const int row = rv + (u & 3)*16;
                const __nv_bfloat16* src = (u < 4) ? g_vh : g_vl;
                cpasync16(vb + (u >> 2)*AV_TILE + row*AVT_STRIDE + jv*16,
                          src + vbase + (size_t)(k0n + row)*128 + jv*8);
            }
            cp_commit();
            asm volatile("cp.async.wait_group 1;" ::: "memory");
        } else {
            asm volatile("cp.async.wait_group 0;" ::: "memory");
        }
        __syncthreads();

        const uint32_t stg = sb + 36864 + (kt & 1)*AKV_STAGE;
        const uint32_t kh_base = stg + br*2*AQ_TILE;
        const uint32_t kl_base = kh_base + AQ_TILE;
        const uint32_t vh_base = stg + 4*AQ_TILE;
        const uint32_t vl_base = vh_base + AV_TILE;

        float sacc[8][4];
#pragma unroll
        for (int g = 0; g < 8; g++)
#pragma unroll
            for (int c = 0; c < 4; c++) sacc[g][c] = 0.f;
#pragma unroll
        for (int ka = 0; ka < 4; ka++) {
            uint32_t ah[4], al[4];
            ldm4(ah, qh_base + qa_off + ka*32);
            ldm4(al, ql_base + qa_off + ka*32);
#pragma unroll
            for (int g2 = 0; g2 < 4; g2++) {
                uint32_t bh4[4], bl4[4];
                ldm4(bh4, kh_base + g2*(16*AKT_STRIDE) + kb_off + ka*32);
                ldm4(bl4, kl_base + g2*(16*AKT_STRIDE) + kb_off + ka*32);
#pragma unroll
                for (int hf = 0; hf < 2; hf++) {
                    float* C = sacc[g2*2 + hf];
                    mma16816(C, ah, bh4[hf*2], bh4[hf*2+1]);
                    mma16816(C, ah, bl4[hf*2], bl4[hf*2+1]);
                    mma16816(C, al, bh4[hf*2], bh4[hf*2+1]);
                }
            }
        }

        const bool diag = (kt == qt);
        float t0 = -1e30f, t1 = -1e30f;
#pragma unroll
        for (int g = 0; g < 8; g++) {
            const int cb = g*8 + (lane & 3)*2;
#pragma unroll
            for (int c = 0; c < 4; c++) {
                float s = sacc[g][c] * SCALE_L2E;
                if (diag) {
                    const int rr = row_l + (c >= 2 ? 8 : 0);
                    const int cc = cb + (c & 1);
                    if (cc > rr) s = -1e30f;
                }
                sacc[g][c] = s;
            }
            t0 = fmaxf(t0, fmaxf(sacc[g][0], sacc[g][1]));
            t1 = fmaxf(t1, fmaxf(sacc[g][2], sacc[g][3]));
        }
        t0 = fmaxf(t0, __shfl_xor_sync(0xffffffffu, t0, 1));
        t0 = fmaxf(t0, __shfl_xor_sync(0xffffffffu, t0, 2));
        t1 = fmaxf(t1, __shfl_xor_sync(0xffffffffu, t1, 1));
        t1 = fmaxf(t1, __shfl_xor_sync(0xffffffffu, t1, 2));
        const float mn0 = fmaxf(m0, t0), mn1 = fmaxf(m1, t1);
        const float alpha0 = exp2f(m0 - mn0), alpha1 = exp2f(m1 - mn1);
        m0 = mn0; m1 = mn1;

        float rs0 = 0.f, rs1 = 0.f;
#pragma unroll
        for (int g = 0; g < 8; g++) {
            float p0 = exp2f(sacc[g][0] - mn0);
            float p1 = exp2f(sacc[g][1] - mn0);
            float p2 = exp2f(sacc[g][2] - mn1);
            float p3 = exp2f(sacc[g][3] - mn1);
            sacc[g][0] = p0; sacc[g][1] = p1; sacc[g][2] = p2; sacc[g][3] = p3;
            rs0 += p0 + p1; rs1 += p2 + p3;
        }
        rs0 += __shfl_xor_sync(0xffffffffu, rs0, 1);
        rs0 += __shfl_xor_sync(0xffffffffu, rs0, 2);
        rs1 += __shfl_xor_sync(0xffffffffu, rs1, 1);
        rs1 += __shfl_xor_sync(0xffffffffu, rs1, 2);
        l0 = l0*alpha0 + rs0;
        l1 = l1*alpha1 + rs1;

#pragma unroll
        for (int n = 0; n < 16; n++) {
            acc[n][0] *= alpha0; acc[n][1] *= alpha0;
            acc[n][2] *= alpha1; acc[n][3] *= alpha1;
        }

#pragma unroll
        for (int ka = 0; ka < 4; ka++) {
            uint32_t ph[4], pl[4];
#pragma unroll
            for (int half = 0; half < 2; half++) {
                const int g = 2*ka + half;
                float v0 = sacc[g][0], v1 = sacc[g][1], v2 = sacc[g][2], v3 = sacc[g][3];
                __nv_bfloat16 b0 = __float2bfloat16(v0), b1v = __float2bfloat16(v1);
                __nv_bfloat16 b2 = __float2bfloat16(v2), b3 = __float2bfloat16(v3);
                __nv_bfloat162 t01 = __halves2bfloat162(b0, b1v);
                __nv_bfloat162 t23 = __halves2bfloat162(b2, b3);
                ph[half*2 + 0] = *(uint32_t*)&t01;
                ph[half*2 + 1] = *(uint32_t*)&t23;
                pl[half*2 + 0] = packbf(v0 - __bfloat162float(b0), v1 - __bfloat162float(b1v));
                pl[half*2 + 1] = packbf(v2 - __bfloat162float(b2), v3 - __bfloat162float(b3));
            }
#pragma unroll
            for (int np = 0; np < 8; np++) {
                uint32_t vh4[4], vl4[4];
                ldm4t(vh4, vh_base + ka*(16*AVT_STRIDE) + vb_off + np*32);
                ldm4t(vl4, vl_base + ka*(16*AVT_STRIDE) + vb_off + np*32);
#pragma unroll
                for (int hf = 0; hf < 2; hf++) {
                    float* C = acc[np*2 + hf];
                    mma16816(C, ph, vh4[hf*2], vh4[hf*2+1]);
                    mma16816(C, ph, vl4[hf*2], vl4[hf*2+1]);
                    mma16816(C, pl, vh4[hf*2], vh4[hf*2+1]);
                }
            }
        }
        __syncthreads();
    }

    const float inv0 = 1.f / l0, inv1 = 1.f / l1;
#pragma unroll
    for (int n = 0; n < 16; n++) {
        acc[n][0] *= inv0; acc[n][1] *= inv0;
        acc[n][2] *= inv1; acc[n][3] *= inv1;
    }

    float* sO = (float*)smem;
    const int rl = row_l, rh = row_l + 8;
    __syncthreads();
    if (br == 1) {
#pragma unroll
        for (int n = 0; n < 16; n++) {
            const int c = n*8 + (lane & 3)*2;
            float2 a; a.x = acc[n][0]; a.y = acc[n][1];
            float2 bvv; bvv.x = acc[n][2]; bvv.y = acc[n][3];
            *(float2*)&sO[rl*128 + c] = a;
            *(float2*)&sO[rh*128 + c] = bvv;
        }
    }
    __syncthreads();
    if (br == 0) {
        const float lam = g_lambda;
        const float osc = 1.f - LAMBDA_INIT_F;
        float ssq0 = 0.f, ssq1 = 0.f;
#pragma unroll
        for (int n = 0; n < 16; n++) {
            const int c = n*8 + (lane & 3)*2;
            float2 o2l = *(float2*)&sO[rl*128 + c];
            float2 o2h = *(float2*)&sO[rh*128 + c];
            acc[n][0] -= lam*o2l.x; acc[n][1] -= lam*o2l.y;
            acc[n][2] -= lam*o2h.x; acc[n][3] -= lam*o2h.y;
            ssq0 += acc[n][0]*acc[n][0] + acc[n][1]*acc[n][1];
            ssq1 += acc[n][2]*acc[n][2] + acc[n][3]*acc[n][3];
        }
        ssq0 += __shfl_xor_sync(0xffffffffu, ssq0, 1);
        ssq0 += __shfl_xor_sync(0xffffffffu, ssq0, 2);
        ssq1 += __shfl_xor_sync(0xffffffffu, ssq1, 1);
        ssq1 += __shfl_xor_sync(0xffffffffu, ssq1, 2);
        const float rms0 = rsqrtf(ssq0 * (1.f/128.f) + 1e-8f);
        const float rms1 = rsqrtf(ssq1 * (1.f/128.f) + 1e-8f);
        const size_t ob_l = ((size_t)(b*SDIM + q0 + rl))*DDIM + h*128;
        const size_t ob_h = ((size_t)(b*SDIM + q0 + rh))*DDIM + h*128;
#pragma unroll
        for (int n = 0; n < 16; n++) {
            const int c = n*8 + (lane & 3)*2;
            float w0 = __ldg(&ln_w[c]), w1 = __ldg(&ln_w[c+1]);
            float bb0 = __ldg(&ln_b[c]), bb1 = __ldg(&ln_b[c+1]);
            float v0 = (acc[n][0]*rms0*w0 + bb0) * osc;
            float v1 = (acc[n][1]*rms0*w1 + bb1) * osc;
            float v2 = (acc[n][2]*rms1*w0 + bb0) * osc;
            float v3 = (acc[n][3]*rms1*w1 + bb1) * osc;
            *(__half2*)&g_attn16[ob_l + c] = __floats2half2_rn(v0, v1);
            *(__half2*)&g_attn16[ob_h + c] = __floats2half2_rn(v2, v3);
        }
    }
}

// ================= layernorm over 1024 (+ optional plain fp16 out) =================
__global__ __launch_bounds__(256) void layernorm_kernel(
    const float* __restrict__ in, const float* __restrict__ w, const float* __restrict__ bb,
    float* __restrict__ out, __half* __restrict__ oh16)
{
    __shared__ float red1[8], red2[8];
    const int row = blockIdx.x;
    const float* x = in + (size_t)row * DDIM;
    float v[4];
    float s = 0.f, s2 = 0.f;
#pragma unroll
    for (int it = 0; it < 4; it++) {
        float t = x[threadIdx.x + it*256];
        v[it] = t; s += t; s2 += t*t;
    }
#pragma unroll
    for (int o = 16; o; o >>= 1) {
        s  += __shfl_xor_sync(0xffffffffu, s,  o);
        s2 += __shfl_xor_sync(0xffffffffu, s2, o);
    }
    const int lane = threadIdx.x & 31, wp = threadIdx.x >> 5;
    if (lane == 0) { red1[wp] = s; red2[wp] = s2; }
    __syncthreads();
    if (wp == 0) {
        s  = (lane < 8) ? red1[lane] : 0.f;
        s2 = (lane < 8) ? red2[lane] : 0.f;
#pragma unroll
        for (int o = 4; o; o >>= 1) {
            s  += __shfl_xor_sync(0xffffffffu, s,  o);
            s2 += __shfl_xor_sync(0xffffffffu, s2, o);
        }
        if (lane == 0) { red1[0] = s * (1.f/1024.f); red2[0] = s2 * (1.f/1024.f); }
    }
    __syncthreads();
    const float mean = red1[0];
    const float var = red2[0] - mean*mean;
    const float rstd = rsqrtf(var + 1e-5f);
#pragma unroll
    for (int it = 0; it < 4; it++) {
        int c = threadIdx.x + it*256;
        size_t idx = (size_t)row*DDIM + c;
        float y = (v[it] - mean)*rstd*w[c] + bb[c];
        out[idx] = y;
        if (oh16) oh16[idx] = __float2half(y);
    }
}

// ================= launch =================
extern "C" void kernel_launch(void* const* d_in, const int* in_sizes, int n_in,
                              void* d_out, int out_size)
{
    (void)in_sizes; (void)n_in; (void)out_size;
    const float* x      = (const float*)d_in[0];
    const float* sigmas = (const float*)d_in[1];
    const float* w_qkv  = (const float*)d_in[2];
    const float* w_out  = (const float*)d_in[3];
    const float* lq1    = (const float*)d_in[4];
    const float* lk1    = (const float*)d_in[5];
    const float* lq2    = (const float*)d_in[6];
    const float* lk2    = (const float*)d_in[7];
    const float* ln_w   = (const float*)d_in[8];
    const float* ln_b   = (const float*)d_in[9];
    const float* lnq_w  = (const float*)d_in[10];
    const float* lnq_b  = (const float*)d_in[11];
    const float* ln1_w  = (const float*)d_in[12];
    const float* ln1_b  = (const float*)d_in[13];
    const float* ln2_w  = (const float*)d_in[14];
    const float* ln2_b  = (const float*)d_in[15];
    const float* w1     = (const float*)d_in[16];
    const float* b1     = (const float*)d_in[17];
    const float* w2     = (const float*)d_in[18];
    const float* b2     = (const float*)d_in[19];
    float* out = (float*)d_out;

    void *p_qkv, *p_tmp1, *p_h, *p_f2;
    void *p_x16, *p_attn16, *p_h16, *p_ff116;
    void *p_wqkvh, *p_wqkvl, *p_wouth, *p_woutl, *p_w1h, *p_w1l, *p_w2h, *p_w2l;
    cudaGetSymbolAddress(&p_qkv,  g_qkv);
    cudaGetSymbolAddress(&p_tmp1, g_tmp1);
    cudaGetSymbolAddress(&p_h,    g_h);
    cudaGetSymbolAddress(&p_f2,   g_f2);
    cudaGetSymbolAddress(&p_x16, g_x16);
    cudaGetSymbolAddress(&p_attn16, g_attn16);
    cudaGetSymbolAddress(&p_h16, g_h16);
    cudaGetSymbolAddress(&p_ff116, g_ff116);
    cudaGetSymbolAddress(&p_wqkvh, g_wqkvT16h); cudaGetSymbolAddress(&p_wqkvl, g_wqkvT16l);
    cudaGetSymbolAddress(&p_wouth, g_woutT16h); cudaGetSymbolAddress(&p_woutl, g_woutT16l);
    cudaGetSymbolAddress(&p_w1h, g_w1T16h);     cudaGetSymbolAddress(&p_w1l, g_w1T16l);
    cudaGetSymbolAddress(&p_w2h, g_w2T16h);     cudaGetSymbolAddress(&p_w2l, g_w2T16l);

    cudaFuncSetAttribute(gemm_f16_kernel, cudaFuncAttributeMaxDynamicSharedMemorySize, GEMMF_SMEM);
    cudaFuncSetAttribute(attn_mma_kernel, cudaFuncAttributeMaxDynamicSharedMemorySize, ATT_SMEM);

    const float inv64 = 0.015625f;

    // --- prep needed before qkv ---
    lambda_kernel<<<1, 32>>>(lq1, lk1, lq2, lk2);
    split_f16_kernel<<<(MROWS*DDIM/4 + 255)/256, 256>>>(x, (__half*)p_x16, MROWS*DDIM/4);
    transpose_split_f16_kernel<<<dim3(3072/32, 1024/32), dim3(32,8)>>>(w_qkv, (__half*)p_wqkvh, (__half*)p_wqkvl, 1024, 3072);

    // qkv = x @ w_qkv (fp16 2-term, weights x64, epilogue /64)
    gemm_f16_kernel<<<dim3(3072/128, 4096/128), 256, GEMMF_SMEM>>>(
        (const __half*)p_x16, (const __half*)p_wqkvh, (const __half*)p_wqkvl,
        (float*)p_qkv, nullptr, MROWS, 3072, 1024, inv64, nullptr, nullptr, 0);

    rope_split_kernel<<<MROWS, 256>>>(sigmas, lnq_w, lnq_b);

    attn_mma_kernel<<<dim3(SDIM/64, HH, BDIM), 256, ATT_SMEM>>>(ln_w, ln_b);

    // --- remaining weight transposes (independent; scheduled here) ---
    transpose_split_f16_kernel<<<dim3(1024/32, 1024/32), dim3(32,8)>>>(w_out, (__half*)p_wouth, (__half*)p_woutl, 1024, 1024);
    transpose_split_f16_kernel<<<dim3(4096/32, 1024/32), dim3(32,8)>>>(w1, (__half*)p_w1h, (__half*)p_w1l, 1024, 4096);
    transpose_split_f16_kernel<<<dim3(1024/32, 4096/32), dim3(32,8)>>>(w2, (__half*)p_w2h, (__half*)p_w2l, 4096, 1024);

    // tmp1 = attn @ w_out + x
    gemm_f16_kernel<<<dim3(1024/128, 4096/128), 256, GEMMF_SMEM>>>(
        (const __half*)p_attn16, (const __half*)p_wouth, (const __half*)p_woutl,
        (float*)p_tmp1, nullptr, MROWS, 1024, 1024, inv64, nullptr, x, 0);

    layernorm_kernel<<<MROWS, 256>>>((const float*)p_tmp1, ln1_w, ln1_b,
        (float*)p_h, (__half*)p_h16);

    // ff1 = silu(h @ w1 + b1) -> plain fp16
    gemm_f16_kernel<<<dim3(4096/128, 4096/128), 256, GEMMF_SMEM>>>(
        (const __half*)p_h16, (const __half*)p_w1h, (const __half*)p_w1l,
        nullptr, (__half*)p_ff116, MROWS, 4096, 1024, inv64, b1, nullptr, 1);

    // f2 = ff1 @ w2 + b2 + h
    gemm_f16_kernel<<<dim3(1024/128, 4096/128), 256, GEMMF_SMEM>>>(
        (const __half*)p_ff116, (const __half*)p_w2h, (const __half*)p_w2l,
        (float*)p_f2, nullptr, MROWS, 1024, 4096, inv64, b2, (const float*)p_h, 0);

    layernorm_kernel<<<MROWS, 256>>>((const float*)p_f2, ln2_w, ln2_b, out, nullptr);
}